// round 6
// baseline (speedup 1.0000x reference)
#include <cuda_runtime.h>
#include <cuda_bf16.h>
#include <cstdint>
#include <math.h>

// Problem constants:
//  x: [16, 512, 64, 64] fp32 == [64 batches][128 ch][4096 px] contiguous
#define NB     64
#define CI     128
#define NPIX   4096
#define KSPLIT 4                 // gram K-split CTAs per batch (K=1024 each)
#define PAD    132               // chain smem stride
#define GSTR   36                // gram smem stride (32 + 4) -> conflict-free
#define ASTR   132               // apply A smem stride (conflict-free for A frags)
#define XSTR   136               // apply X smem stride (conflict-free for B frags)

// ---------------- tf32 helpers ----------------
__device__ __forceinline__ void tf32split(float v, float& h, float& l) {
    uint32_t hb;
    asm("cvt.rna.tf32.f32 %0, %1;" : "=r"(hb) : "f"(v));
    h = __uint_as_float(hb);
    float lr = v - h;
    uint32_t lb;
    asm("cvt.rna.tf32.f32 %0, %1;" : "=r"(lb) : "f"(lr));
    l = __uint_as_float(lb);
}

// D += A(16x8,row) * B(8x8,col)   tf32 x f32-accum
__device__ __forceinline__ void mma8(float* d, const float* a, const float* b) {
    asm volatile(
        "mma.sync.aligned.m16n8k8.row.col.f32.tf32.tf32.f32 "
        "{%0,%1,%2,%3}, {%4,%5,%6,%7}, {%8,%9}, {%0,%1,%2,%3};"
        : "+f"(d[0]), "+f"(d[1]), "+f"(d[2]), "+f"(d[3])
        : "r"(__float_as_uint(a[0])), "r"(__float_as_uint(a[1])),
          "r"(__float_as_uint(a[2])), "r"(__float_as_uint(a[3])),
          "r"(__float_as_uint(b[0])), "r"(__float_as_uint(b[1])));
}

// ---------------- scratch ----------------
__device__ float g_Gpart[NB * KSPLIT * CI * CI];   // partial E (G = (E+E^T)/2)
__device__ float g_spart[NB * KSPLIT * CI];        // partial row sums
__device__ float g_Ah[NB * CI * CI];               // A'' tf32-hi
__device__ float g_Al[NB * CI * CI];               // A'' tf32-lo
__device__ float g_bvec[NB * CI];                  // folded bias b'

// =====================================================================
// Kernel 1: partial E = H H^T + H (2L)^T via mma.sync (2 products).
// grid (KSPLIT, NB), 256 threads, 2 CTAs/SM. K=1024 px, 32 chunks of
// 32 px, double-buffered dynamic smem, one barrier per chunk.
// =====================================================================
#define GK_BUF  (128 * GSTR)                        // floats per buffer
#define GK_SMEM (4 * GK_BUF * 4)                    // 73728 B

__device__ __forceinline__ float gram_split16(const float4* v,
                                              float* bH, float* bL,
                                              int lrow, int lseg)
{
    float sum = 0.f;
#pragma unroll
    for (int q = 0; q < 4; q++) {
        float va[4] = {v[q].x, v[q].y, v[q].z, v[q].w};
        float h[4], l[4];
#pragma unroll
        for (int j = 0; j < 4; j++) {
            tf32split(va[j], h[j], l[j]);
            l[j] *= 2.0f;
            sum += va[j];
        }
        *(float4*)&bH[lrow * GSTR + lseg + 4 * q] = make_float4(h[0], h[1], h[2], h[3]);
        *(float4*)&bL[lrow * GSTR + lseg + 4 * q] = make_float4(l[0], l[1], l[2], l[3]);
    }
    return sum;
}

__global__ void __launch_bounds__(256, 2)
gram_kernel(const float* __restrict__ X)
{
    extern __shared__ float gsm[];
    float* sHb[2] = {gsm, gsm + GK_BUF};
    float* sLb[2] = {gsm + 2 * GK_BUF, gsm + 3 * GK_BUF};
    __shared__ float sred[256];

    const int t = threadIdx.x;
    const int lane = t & 31, w = t >> 5;
    const int wr = (w >> 2) * 64, wc = (w & 3) * 32;
    const int qr = lane >> 2, qc = lane & 3;
    const int kc = blockIdx.x, bb = blockIdx.y;

    const float* Xb = X + (size_t)bb * CI * NPIX + (size_t)kc * 1024;
    const int lrow = t >> 1, lseg = (t & 1) * 16;
    const float* Xr = Xb + (size_t)lrow * NPIX;

    float acc[4][4][4];
#pragma unroll
    for (int m = 0; m < 4; m++)
#pragma unroll
        for (int n = 0; n < 4; n++)
#pragma unroll
            for (int r = 0; r < 4; r++) acc[m][n][r] = 0.f;
    float mysum = 0.f;

    // preload chunk 0
    {
        float4 v[4];
#pragma unroll
        for (int q = 0; q < 4; q++) v[q] = *(const float4*)(Xr + lseg + 4 * q);
        mysum += gram_split16(v, sHb[0], sLb[0], lrow, lseg);
    }
    __syncthreads();

    for (int ch = 0; ch < 32; ch++) {
        const int b = ch & 1;
        float4 nx[4];
        if (ch < 31) {
#pragma unroll
            for (int q = 0; q < 4; q++)
                nx[q] = *(const float4*)(Xr + (ch + 1) * 32 + lseg + 4 * q);
        }

        const float* cH = sHb[b];
        const float* cL = sLb[b];
#pragma unroll
        for (int ks = 0; ks < 4; ks++) {
            const int k0 = ks * 8;
            float Ah[4][4];
#pragma unroll
            for (int m = 0; m < 4; m++) {
                const int ar = wr + m * 16 + qr;
                Ah[m][0] = cH[ar * GSTR + k0 + qc];
                Ah[m][1] = cH[(ar + 8) * GSTR + k0 + qc];
                Ah[m][2] = cH[ar * GSTR + k0 + qc + 4];
                Ah[m][3] = cH[(ar + 8) * GSTR + k0 + qc + 4];
            }
#pragma unroll
            for (int n = 0; n < 4; n++) {
                const int br = wc + n * 8 + qr;
                float Bh[2], Bl[2];
                Bh[0] = cH[br * GSTR + k0 + qc];
                Bh[1] = cH[br * GSTR + k0 + qc + 4];
                Bl[0] = cL[br * GSTR + k0 + qc];
                Bl[1] = cL[br * GSTR + k0 + qc + 4];
#pragma unroll
                for (int m = 0; m < 4; m++) {
                    mma8(acc[m][n], Ah[m], Bh);
                    mma8(acc[m][n], Ah[m], Bl);
                }
            }
        }

        if (ch < 31)
            mysum += gram_split16(nx, sHb[b ^ 1], sLb[b ^ 1], lrow, lseg);
        __syncthreads();
    }

    // row sums
    sred[t] = mysum;
    __syncthreads();
    if (t < 128)
        g_spart[(bb * KSPLIT + kc) * CI + t] = sred[2 * t] + sred[2 * t + 1];

    // write partial E
    float* P = g_Gpart + ((size_t)(bb * KSPLIT + kc)) * CI * CI;
#pragma unroll
    for (int m = 0; m < 4; m++) {
        const int r0 = wr + m * 16 + qr;
#pragma unroll
        for (int n = 0; n < 4; n++) {
            const int c0 = wc + n * 8 + qc * 2;
            *(float2*)(P + (size_t)r0 * CI + c0)       = make_float2(acc[m][n][0], acc[m][n][1]);
            *(float2*)(P + (size_t)(r0 + 8) * CI + c0) = make_float2(acc[m][n][2], acc[m][n][3]);
        }
    }
}

// =====================================================================
// Kernel 2: chain (fp32 CUDA cores) + tf32 split of A''.  (proven path)
// =====================================================================
__device__ __forceinline__ void mg128(const float* U, const float* V, float* O, int t)
{
    const int tr = (t >> 4) << 3;
    const int tc = (t & 15) << 3;
    float acc[8][8];
#pragma unroll
    for (int i = 0; i < 8; i++)
#pragma unroll
        for (int j = 0; j < 8; j++) acc[i][j] = 0.f;
#pragma unroll 4
    for (int e = 0; e < 128; e++) {
        float4 a0 = *(const float4*)(U + e * PAD + tr);
        float4 a1 = *(const float4*)(U + e * PAD + tr + 4);
        float4 b0 = *(const float4*)(V + e * PAD + tc);
        float4 b1 = *(const float4*)(V + e * PAD + tc + 4);
        float a[8] = {a0.x, a0.y, a0.z, a0.w, a1.x, a1.y, a1.z, a1.w};
        float b[8] = {b0.x, b0.y, b0.z, b0.w, b1.x, b1.y, b1.z, b1.w};
#pragma unroll
        for (int i = 0; i < 8; i++)
#pragma unroll
            for (int j = 0; j < 8; j++) acc[i][j] += a[i] * b[j];
    }
#pragma unroll
    for (int i = 0; i < 8; i++)
#pragma unroll
        for (int j = 0; j < 8; j++)
            O[(tr + i) * PAD + (tc + j)] = acc[i][j];
}

__device__ __forceinline__ void mg128_final(const float* U, const float* V,
                                            float* gAh, float* gAl,
                                            const float* scale, int t)
{
    const int tr = (t >> 4) << 3;
    const int tc = (t & 15) << 3;
    float acc[8][8];
#pragma unroll
    for (int i = 0; i < 8; i++)
#pragma unroll
        for (int j = 0; j < 8; j++) acc[i][j] = 0.f;
#pragma unroll 4
    for (int e = 0; e < 128; e++) {
        float4 a0 = *(const float4*)(U + e * PAD + tr);
        float4 a1 = *(const float4*)(U + e * PAD + tr + 4);
        float4 b0 = *(const float4*)(V + e * PAD + tc);
        float4 b1 = *(const float4*)(V + e * PAD + tc + 4);
        float a[8] = {a0.x, a0.y, a0.z, a0.w, a1.x, a1.y, a1.z, a1.w};
        float b[8] = {b0.x, b0.y, b0.z, b0.w, b1.x, b1.y, b1.z, b1.w};
#pragma unroll
        for (int i = 0; i < 8; i++)
#pragma unroll
            for (int j = 0; j < 8; j++) acc[i][j] += a[i] * b[j];
    }
#pragma unroll
    for (int i = 0; i < 8; i++) {
        float sc = scale[tr + i];
#pragma unroll
        for (int j = 0; j < 8; j++) {
            int r = tr + i, c = tc + j;
            float val = sc * acc[i][j] + ((r == c) ? 1.0f : 0.0f);
            float h, l;
            tf32split(val, h, l);
            gAh[r * CI + c] = h;
            gAl[r * CI + c] = l;
        }
    }
}

__global__ void __launch_bounds__(256)
chain_kernel(const float* __restrict__ theta_w, const float* __restrict__ theta_b,
             const float* __restrict__ phi_w,   const float* __restrict__ phi_b,
             const float* __restrict__ g_w,     const float* __restrict__ g_b,
             const float* __restrict__ W_w,     const float* __restrict__ W_b,
             const float* __restrict__ bn_gamma, const float* __restrict__ bn_beta,
             const float* __restrict__ bn_mean,  const float* __restrict__ bn_var)
{
    extern __shared__ float dsm[];
    float* B0 = dsm;
    float* B1 = dsm + CI * PAD;
    float* B2 = dsm + 2 * CI * PAD;

    __shared__ float sv_s[CI], sv_u[CI], sv_q[CI], sv_tb[CI],
                     sv_gb[CI], sv_c[CI], sv_scale[CI];

    const int t  = threadIdx.x;
    const int bb = blockIdx.x;

    // --- stage S = sum_ks E_ks into B2 (coalesced); theta^T into B1 ---
    const float* Gp = g_Gpart + (size_t)bb * KSPLIT * CI * CI;
    for (int idx = t; idx < CI * CI; idx += 256) {
        float v = 0.f;
#pragma unroll
        for (int ks = 0; ks < KSPLIT; ks++) v += Gp[ks * CI * CI + idx];
        B2[(idx >> 7) * PAD + (idx & 127)] = v;
    }
    if (t < CI) {
        float v = 0.f;
#pragma unroll
        for (int ks = 0; ks < KSPLIT; ks++) v += g_spart[(bb * KSPLIT + ks) * CI + t];
        sv_s[t]  = v;
        sv_tb[t] = theta_b[t];
        sv_gb[t] = g_b[t];
        sv_scale[t] = bn_gamma[t] * rsqrtf(bn_var[t] + 1e-5f);
    }
    for (int idx = t; idx < CI * CI; idx += 256) {
        int r = idx >> 7, c = idx & 127;
        B1[c * PAD + r] = theta_w[idx];
    }
    __syncthreads();

    // --- symmetrize: G = (S + S^T)/2 into B0;  q from theta^T ---
    for (int idx = t; idx < CI * CI; idx += 256) {
        int r = idx >> 7, c = idx & 127;
        B0[r * PAD + c] = 0.5f * (B2[r * PAD + c] + B2[c * PAD + r]);
    }
    if (t < CI) {
        float v = 0.f;
#pragma unroll 8
        for (int e = 0; e < 128; e++) v += B1[e * PAD + t] * sv_s[e];
        sv_q[t] = v + 4096.0f * sv_tb[t];
    }
    __syncthreads();

    mg128(B0, B1, B2, t);          // T1 = G theta^T
    __syncthreads();

    for (int idx = t; idx < CI * CI; idx += 256) {
        int r = idx >> 7, c = idx & 127;
        B0[c * PAD + r] = phi_w[idx];
    }
    __syncthreads();
    if (t < CI) {
        float v = 0.f;
#pragma unroll 8
        for (int e = 0; e < 128; e++) v += B0[e * PAD + t] * sv_s[e];
        sv_u[t] = v;
    }
    __syncthreads();

    mg128(B0, B2, B1, t);          // L = phi T1
    __syncthreads();

    if (t < CI) {
        float w1 = sv_u[t];
        float w2 = phi_b[t];
        float* rowp = B1 + t * PAD;
        float mx = -1e30f;
#pragma unroll 8
        for (int d = 0; d < 128; d++) {
            float v = rowp[d] + w1 * sv_tb[d] + w2 * sv_q[d];
            rowp[d] = v;
            mx = fmaxf(mx, v);
        }
        float ssum = 0.f;
#pragma unroll 8
        for (int d = 0; d < 128; d++) {
            float ev = expf(rowp[d] - mx);
            rowp[d] = ev;
            ssum += ev;
        }
        float inv = 1.0f / ssum;
        float cacc = 0.f;
#pragma unroll 8
        for (int d = 0; d < 128; d++) {
            float f = rowp[d] * inv;
            B2[d * PAD + t] = f;
            cacc += f * sv_gb[d];
        }
        sv_c[t] = cacc;
    }
    __syncthreads();

    for (int idx = t; idx < CI * CI; idx += 256)
        B0[(idx >> 7) * PAD + (idx & 127)] = g_w[idx];
    __syncthreads();

    mg128(B2, B0, B1, t);          // M = f g_w
    __syncthreads();

    for (int idx = t; idx < CI * CI; idx += 256) {
        int r = idx >> 7, c = idx & 127;
        B2[c * PAD + r] = W_w[idx];
    }
    __syncthreads();

    if (t < CI) {
        float b0 = 0.f;
#pragma unroll 8
        for (int e = 0; e < 128; e++) b0 += B2[e * PAD + t] * sv_c[e];
        float sc = sv_scale[t];
        g_bvec[bb * CI + t] = sc * (b0 + W_b[t]) + bn_beta[t] - bn_mean[t] * sc;
    }

    mg128_final(B2, B1, g_Ah + (size_t)bb * CI * CI, g_Al + (size_t)bb * CI * CI,
                sv_scale, t);
}

// =====================================================================
// Kernel 3: Z = A'' X + b' via mma.sync tf32x3.
// grid (32, 64), 512 threads (16 warps -> 4/SMSP). CTA tile 128ch x 128px,
// warp tile 32x32 (m2 x n4). A'' resident; X: 4 chunks of 32k x 128px,
// double-buffered, one barrier per chunk, epilogue once.
// =====================================================================
#define AP_XBUF (32 * XSTR)
#define AP_SMEM ((2 * 128 * ASTR + 4 * AP_XBUF) * 4)   // 204800 B

__global__ void __launch_bounds__(512)
apply_kernel(const float* __restrict__ X, float* __restrict__ Z)
{
    extern __shared__ float apsm[];
    float* sAh = apsm;                         // [128][ASTR]
    float* sAl = sAh + 128 * ASTR;
    float* sXh[2] = {sAl + 128 * ASTR, sAl + 128 * ASTR + AP_XBUF};
    float* sXl[2] = {sAl + 128 * ASTR + 2 * AP_XBUF,
                     sAl + 128 * ASTR + 3 * AP_XBUF};

    const int t = threadIdx.x;
    const int lane = t & 31, w = t >> 5;
    const int wr = (w >> 2) * 32, wc = (w & 3) * 32;
    const int qr = lane >> 2, qc = lane & 3;
    const int bb = blockIdx.y;
    const int n0 = blockIdx.x * 128;

    // ---- stage A'' hi/lo resident (coalesced float4) ----
    {
        const int row = t >> 2, seg = (t & 3) * 32;
        const float* Ah = g_Ah + (size_t)bb * CI * CI + row * CI + seg;
        const float* Al = g_Al + (size_t)bb * CI * CI + row * CI + seg;
#pragma unroll
        for (int j = 0; j < 8; j++) {
            *(float4*)&sAh[row * ASTR + seg + 4 * j] = *(const float4*)(Ah + 4 * j);
            *(float4*)&sAl[row * ASTR + seg + 4 * j] = *(const float4*)(Al + 4 * j);
        }
    }

    float bias[2][2];
#pragma unroll
    for (int m = 0; m < 2; m++) {
        bias[m][0] = g_bvec[bb * CI + wr + m * 16 + qr];
        bias[m][1] = g_bvec[bb * CI + wr + m * 16 + qr + 8];
    }

    const float* Xb = X + (size_t)bb * CI * NPIX;
    float* Zb = Z + (size_t)bb * CI * NPIX;

    const int lch = t >> 4, lpx = (t & 15) * 8;   // X loader: 8 px per thread

    float acc[2][4][4];
#pragma unroll
    for (int m = 0; m < 2; m++)
#pragma unroll
        for (int n = 0; n < 4; n++)
#pragma unroll
            for (int r = 0; r < 4; r++) acc[m][n][r] = 0.f;

    // preload chunk 0 (channels 0..31)
    {
        const float* src = Xb + (size_t)lch * NPIX + n0 + lpx;
#pragma unroll
        for (int j = 0; j < 2; j++) {
            float4 v = *(const float4*)(src + 4 * j);
            float h0, l0, h1, l1, h2, l2, h3, l3;
            tf32split(v.x, h0, l0); tf32split(v.y, h1, l1);
            tf32split(v.z, h2, l2); tf32split(v.w, h3, l3);
            *(float4*)&sXh[0][lch * XSTR + lpx + 4 * j] = make_float4(h0, h1, h2, h3);
            *(float4*)&sXl[0][lch * XSTR + lpx + 4 * j] = make_float4(l0, l1, l2, l3);
        }
    }
    __syncthreads();

    for (int g = 0; g < 4; g++) {
        const int b = g & 1;
        float4 nx[2];
        if (g < 3) {
            const float* src = Xb + (size_t)((g + 1) * 32 + lch) * NPIX + n0 + lpx;
#pragma unroll
            for (int j = 0; j < 2; j++) nx[j] = *(const float4*)(src + 4 * j);
        }

#pragma unroll
        for (int ks = 0; ks < 4; ks++) {
            const int kl = ks * 8;
            const int kg = g * 32 + kl;
            float Ahf[2][4], Alf[2][4];
#pragma unroll
            for (int m = 0; m < 2; m++) {
                const int ar = wr + m * 16 + qr;
                Ahf[m][0] = sAh[ar * ASTR + kg + qc];
                Ahf[m][1] = sAh[(ar + 8) * ASTR + kg + qc];
                Ahf[m][2] = sAh[ar * ASTR + kg + qc + 4];
                Ahf[m][3] = sAh[(ar + 8) * ASTR + kg + qc + 4];
                Alf[m][0] = sAl[ar * ASTR + kg + qc];
                Alf[m][1] = sAl[(ar + 8) * ASTR + kg + qc];
                Alf[m][2] = sAl[ar * ASTR + kg + qc + 4];
                Alf[m][3] = sAl[(ar + 8) * ASTR + kg + qc + 4];
            }
#pragma unroll
            for (int n = 0; n < 4; n++) {
                const int bpx = wc + n * 8 + qr;
                float Bh[2], Bl[2];
                Bh[0] = sXh[b][(kl + qc) * XSTR + bpx];
                Bh[1] = sXh[b][(kl + qc + 4) * XSTR + bpx];
                Bl[0] = sXl[b][(kl + qc) * XSTR + bpx];
                Bl[1] = sXl[b][(kl + qc + 4) * XSTR + bpx];
#pragma unroll
                for (int m = 0; m < 2; m++) {
                    mma8(acc[m][n], Ahf[m], Bh);
                    mma8(acc[m][n], Ahf[m], Bl);
                    mma8(acc[m][n], Alf[m], Bh);
                }
            }
        }

        if (g < 3) {
#pragma unroll
            for (int j = 0; j < 2; j++) {
                float4 v = nx[j];
                float h0, l0, h1, l1, h2, l2, h3, l3;
                tf32split(v.x, h0, l0); tf32split(v.y, h1, l1);
                tf32split(v.z, h2, l2); tf32split(v.w, h3, l3);
                *(float4*)&sXh[b ^ 1][lch * XSTR + lpx + 4 * j] = make_float4(h0, h1, h2, h3);
                *(float4*)&sXl[b ^ 1][lch * XSTR + lpx + 4 * j] = make_float4(l0, l1, l2, l3);
            }
        }
        __syncthreads();
    }

    // ---- epilogue: bias + store ----
#pragma unroll
    for (int m = 0; m < 2; m++) {
        const int r0 = wr + m * 16 + qr;
#pragma unroll
        for (int n = 0; n < 4; n++) {
            const int c0 = n0 + wc + n * 8 + qc * 2;
            *(float2*)(Zb + (size_t)r0 * NPIX + c0) =
                make_float2(acc[m][n][0] + bias[m][0], acc[m][n][1] + bias[m][0]);
            *(float2*)(Zb + (size_t)(r0 + 8) * NPIX + c0) =
                make_float2(acc[m][n][2] + bias[m][1], acc[m][n][3] + bias[m][1]);
        }
    }
}

// =====================================================================
extern "C" void kernel_launch(void* const* d_in, const int* in_sizes, int n_in,
                              void* d_out, int out_size)
{
    (void)in_sizes; (void)n_in; (void)out_size;
    const float* x        = (const float*)d_in[0];
    const float* theta_w  = (const float*)d_in[1];
    const float* theta_b  = (const float*)d_in[2];
    const float* phi_w    = (const float*)d_in[3];
    const float* phi_b    = (const float*)d_in[4];
    const float* g_w      = (const float*)d_in[5];
    const float* g_b      = (const float*)d_in[6];
    const float* W_w      = (const float*)d_in[7];
    const float* W_b      = (const float*)d_in[8];
    const float* bn_gamma = (const float*)d_in[9];
    const float* bn_beta  = (const float*)d_in[10];
    const float* bn_mean  = (const float*)d_in[11];
    const float* bn_var   = (const float*)d_in[12];
    float* out = (float*)d_out;

    const int smem_chain = 3 * CI * PAD * (int)sizeof(float);  // 202752
    cudaFuncSetAttribute(gram_kernel,
                         cudaFuncAttributeMaxDynamicSharedMemorySize, GK_SMEM);
    cudaFuncSetAttribute(chain_kernel,
                         cudaFuncAttributeMaxDynamicSharedMemorySize, smem_chain);
    cudaFuncSetAttribute(apply_kernel,
                         cudaFuncAttributeMaxDynamicSharedMemorySize, AP_SMEM);

    gram_kernel<<<dim3(KSPLIT, NB), 256, GK_SMEM>>>(x);
    chain_kernel<<<NB, 256, smem_chain>>>(theta_w, theta_b, phi_w, phi_b,
                                          g_w, g_b, W_w, W_b,
                                          bn_gamma, bn_beta, bn_mean, bn_var);
    apply_kernel<<<dim3(NPIX / 128, NB), 512, AP_SMEM>>>(x, out);
}

// round 7
// speedup vs baseline: 1.1059x; 1.1059x over previous
#include <cuda_runtime.h>
#include <cuda_bf16.h>
#include <cstdint>
#include <math.h>

// Problem constants:
//  x: [16, 512, 64, 64] fp32 == [64 batches][128 ch][4096 px] contiguous
#define NB     64
#define CI     128
#define NPIX   4096
#define KSPLIT 8                 // gram K-split CTAs per batch (K=512 each)
#define PAD    132               // chain smem stride
#define GSTR   20                // gram smem stride (16 + 4)
#define ASTR   132               // apply A smem stride (conflict-free A frags)
#define XST    264               // apply X smem stride (264%32==8 -> conflict-free B frags)

// ---------------- tf32 helpers ----------------
__device__ __forceinline__ void tf32split(float v, float& h, float& l) {
    uint32_t hb;
    asm("cvt.rna.tf32.f32 %0, %1;" : "=r"(hb) : "f"(v));
    h = __uint_as_float(hb);
    float lr = v - h;
    uint32_t lb;
    asm("cvt.rna.tf32.f32 %0, %1;" : "=r"(lb) : "f"(lr));
    l = __uint_as_float(lb);
}

// D += A(16x8,row) * B(8x8,col)   tf32 x f32-accum
__device__ __forceinline__ void mma8(float* d, const float* a, const float* b) {
    asm volatile(
        "mma.sync.aligned.m16n8k8.row.col.f32.tf32.tf32.f32 "
        "{%0,%1,%2,%3}, {%4,%5,%6,%7}, {%8,%9}, {%0,%1,%2,%3};"
        : "+f"(d[0]), "+f"(d[1]), "+f"(d[2]), "+f"(d[3])
        : "r"(__float_as_uint(a[0])), "r"(__float_as_uint(a[1])),
          "r"(__float_as_uint(a[2])), "r"(__float_as_uint(a[3])),
          "r"(__float_as_uint(b[0])), "r"(__float_as_uint(b[1])));
}

// ---------------- scratch ----------------
__device__ float g_Gpart[NB * KSPLIT * CI * CI];   // partial E (G = (E+E^T)/2)
__device__ float g_spart[NB * KSPLIT * CI];        // partial row sums
__device__ float g_Ah[NB * CI * CI];               // A'' tf32-hi
__device__ float g_Al[NB * CI * CI];               // A'' tf32-lo
__device__ float g_bvec[NB * CI];                  // folded bias b'

// =====================================================================
// Kernel 1 (round-5 proven, 121us): partial E = H H^T + H (2L)^T.
// grid (KSPLIT, NB), 256 threads, 2 CTAs/SM. 32 chunks of 16 px.
// =====================================================================
__device__ __forceinline__ float gram_split(float4 v0, float4 v1,
                                            float* bH, float* bL, int lrow, int lseg)
{
    float va[8] = {v0.x, v0.y, v0.z, v0.w, v1.x, v1.y, v1.z, v1.w};
    float h[8], l[8];
#pragma unroll
    for (int j = 0; j < 8; j++) {
        tf32split(va[j], h[j], l[j]);
        l[j] *= 2.0f;
    }
    *(float4*)&bH[lrow * GSTR + lseg]     = make_float4(h[0], h[1], h[2], h[3]);
    *(float4*)&bH[lrow * GSTR + lseg + 4] = make_float4(h[4], h[5], h[6], h[7]);
    *(float4*)&bL[lrow * GSTR + lseg]     = make_float4(l[0], l[1], l[2], l[3]);
    *(float4*)&bL[lrow * GSTR + lseg + 4] = make_float4(l[4], l[5], l[6], l[7]);
    return va[0] + va[1] + va[2] + va[3] + va[4] + va[5] + va[6] + va[7];
}

__global__ void __launch_bounds__(256, 2)
gram_kernel(const float* __restrict__ X)
{
    __shared__ float sH[2][128 * GSTR];
    __shared__ float sL[2][128 * GSTR];
    __shared__ float sred[256];

    const int t = threadIdx.x;
    const int lane = t & 31, w = t >> 5;
    const int wr = (w >> 2) * 64, wc = (w & 3) * 32;
    const int qr = lane >> 2, qc = lane & 3;
    const int kc = blockIdx.x, bb = blockIdx.y;

    const float* Xb = X + (size_t)bb * CI * NPIX + (size_t)kc * 512;
    const int lrow = t >> 1, lseg = (t & 1) * 8;
    const float* Xr = Xb + (size_t)lrow * NPIX;

    float acc[4][4][4];
#pragma unroll
    for (int m = 0; m < 4; m++)
#pragma unroll
        for (int n = 0; n < 4; n++)
#pragma unroll
            for (int r = 0; r < 4; r++) acc[m][n][r] = 0.f;
    float mysum = 0.f;

    {
        float4 v0 = *(const float4*)(Xr + lseg);
        float4 v1 = *(const float4*)(Xr + lseg + 4);
        mysum += gram_split(v0, v1, sH[0], sL[0], lrow, lseg);
    }
    __syncthreads();

    for (int ch = 0; ch < 32; ch++) {
        const int b = ch & 1;
        float4 n0, n1;
        if (ch < 31) {
            n0 = *(const float4*)(Xr + (ch + 1) * 16 + lseg);
            n1 = *(const float4*)(Xr + (ch + 1) * 16 + lseg + 4);
        }

        const float* cH = sH[b];
        const float* cL = sL[b];
#pragma unroll
        for (int ks = 0; ks < 2; ks++) {
            const int k0 = ks * 8;
            float Ah[4][4];
#pragma unroll
            for (int m = 0; m < 4; m++) {
                const int ar = wr + m * 16 + qr;
                Ah[m][0] = cH[ar * GSTR + k0 + qc];
                Ah[m][1] = cH[(ar + 8) * GSTR + k0 + qc];
                Ah[m][2] = cH[ar * GSTR + k0 + qc + 4];
                Ah[m][3] = cH[(ar + 8) * GSTR + k0 + qc + 4];
            }
#pragma unroll
            for (int n = 0; n < 4; n++) {
                const int br = wc + n * 8 + qr;
                float Bh[2], Bl[2];
                Bh[0] = cH[br * GSTR + k0 + qc];
                Bh[1] = cH[br * GSTR + k0 + qc + 4];
                Bl[0] = cL[br * GSTR + k0 + qc];
                Bl[1] = cL[br * GSTR + k0 + qc + 4];
#pragma unroll
                for (int m = 0; m < 4; m++) {
                    mma8(acc[m][n], Ah[m], Bh);
                    mma8(acc[m][n], Ah[m], Bl);
                }
            }
        }

        if (ch < 31)
            mysum += gram_split(n0, n1, sH[b ^ 1], sL[b ^ 1], lrow, lseg);
        __syncthreads();
    }

    sred[t] = mysum;
    __syncthreads();
    if (t < 128)
        g_spart[(bb * KSPLIT + kc) * CI + t] = sred[2 * t] + sred[2 * t + 1];

    float* P = g_Gpart + ((size_t)(bb * KSPLIT + kc)) * CI * CI;
#pragma unroll
    for (int m = 0; m < 4; m++) {
        const int r0 = wr + m * 16 + qr;
#pragma unroll
        for (int n = 0; n < 4; n++) {
            const int c0 = wc + n * 8 + qc * 2;
            *(float2*)(P + (size_t)r0 * CI + c0)       = make_float2(acc[m][n][0], acc[m][n][1]);
            *(float2*)(P + (size_t)(r0 + 8) * CI + c0) = make_float2(acc[m][n][2], acc[m][n][3]);
        }
    }
}

// =====================================================================
// Kernel 2: chain (fp32 CUDA cores) + tf32 split of A''.  (proven path)
// =====================================================================
__device__ __forceinline__ void mg128(const float* U, const float* V, float* O, int t)
{
    const int tr = (t >> 4) << 3;
    const int tc = (t & 15) << 3;
    float acc[8][8];
#pragma unroll
    for (int i = 0; i < 8; i++)
#pragma unroll
        for (int j = 0; j < 8; j++) acc[i][j] = 0.f;
#pragma unroll 4
    for (int e = 0; e < 128; e++) {
        float4 a0 = *(const float4*)(U + e * PAD + tr);
        float4 a1 = *(const float4*)(U + e * PAD + tr + 4);
        float4 b0 = *(const float4*)(V + e * PAD + tc);
        float4 b1 = *(const float4*)(V + e * PAD + tc + 4);
        float a[8] = {a0.x, a0.y, a0.z, a0.w, a1.x, a1.y, a1.z, a1.w};
        float b[8] = {b0.x, b0.y, b0.z, b0.w, b1.x, b1.y, b1.z, b1.w};
#pragma unroll
        for (int i = 0; i < 8; i++)
#pragma unroll
            for (int j = 0; j < 8; j++) acc[i][j] += a[i] * b[j];
    }
#pragma unroll
    for (int i = 0; i < 8; i++)
#pragma unroll
        for (int j = 0; j < 8; j++)
            O[(tr + i) * PAD + (tc + j)] = acc[i][j];
}

__device__ __forceinline__ void mg128_final(const float* U, const float* V,
                                            float* gAh, float* gAl,
                                            const float* scale, int t)
{
    const int tr = (t >> 4) << 3;
    const int tc = (t & 15) << 3;
    float acc[8][8];
#pragma unroll
    for (int i = 0; i < 8; i++)
#pragma unroll
        for (int j = 0; j < 8; j++) acc[i][j] = 0.f;
#pragma unroll 4
    for (int e = 0; e < 128; e++) {
        float4 a0 = *(const float4*)(U + e * PAD + tr);
        float4 a1 = *(const float4*)(U + e * PAD + tr + 4);
        float4 b0 = *(const float4*)(V + e * PAD + tc);
        float4 b1 = *(const float4*)(V + e * PAD + tc + 4);
        float a[8] = {a0.x, a0.y, a0.z, a0.w, a1.x, a1.y, a1.z, a1.w};
        float b[8] = {b0.x, b0.y, b0.z, b0.w, b1.x, b1.y, b1.z, b1.w};
#pragma unroll
        for (int i = 0; i < 8; i++)
#pragma unroll
            for (int j = 0; j < 8; j++) acc[i][j] += a[i] * b[j];
    }
#pragma unroll
    for (int i = 0; i < 8; i++) {
        float sc = scale[tr + i];
#pragma unroll
        for (int j = 0; j < 8; j++) {
            int r = tr + i, c = tc + j;
            float val = sc * acc[i][j] + ((r == c) ? 1.0f : 0.0f);
            float h, l;
            tf32split(val, h, l);
            gAh[r * CI + c] = h;
            gAl[r * CI + c] = l;
        }
    }
}

__global__ void __launch_bounds__(256)
chain_kernel(const float* __restrict__ theta_w, const float* __restrict__ theta_b,
             const float* __restrict__ phi_w,   const float* __restrict__ phi_b,
             const float* __restrict__ g_w,     const float* __restrict__ g_b,
             const float* __restrict__ W_w,     const float* __restrict__ W_b,
             const float* __restrict__ bn_gamma, const float* __restrict__ bn_beta,
             const float* __restrict__ bn_mean,  const float* __restrict__ bn_var)
{
    extern __shared__ float dsm[];
    float* B0 = dsm;
    float* B1 = dsm + CI * PAD;
    float* B2 = dsm + 2 * CI * PAD;

    __shared__ float sv_s[CI], sv_u[CI], sv_q[CI], sv_tb[CI],
                     sv_gb[CI], sv_c[CI], sv_scale[CI];

    const int t  = threadIdx.x;
    const int bb = blockIdx.x;

    const float* Gp = g_Gpart + (size_t)bb * KSPLIT * CI * CI;
    for (int idx = t; idx < CI * CI; idx += 256) {
        float v = 0.f;
#pragma unroll
        for (int ks = 0; ks < KSPLIT; ks++) v += Gp[ks * CI * CI + idx];
        B2[(idx >> 7) * PAD + (idx & 127)] = v;
    }
    if (t < CI) {
        float v = 0.f;
#pragma unroll
        for (int ks = 0; ks < KSPLIT; ks++) v += g_spart[(bb * KSPLIT + ks) * CI + t];
        sv_s[t]  = v;
        sv_tb[t] = theta_b[t];
        sv_gb[t] = g_b[t];
        sv_scale[t] = bn_gamma[t] * rsqrtf(bn_var[t] + 1e-5f);
    }
    for (int idx = t; idx < CI * CI; idx += 256) {
        int r = idx >> 7, c = idx & 127;
        B1[c * PAD + r] = theta_w[idx];
    }
    __syncthreads();

    // symmetrize: G = (S + S^T)/2 into B0;  q from theta^T
    for (int idx = t; idx < CI * CI; idx += 256) {
        int r = idx >> 7, c = idx & 127;
        B0[r * PAD + c] = 0.5f * (B2[r * PAD + c] + B2[c * PAD + r]);
    }
    if (t < CI) {
        float v = 0.f;
#pragma unroll 8
        for (int e = 0; e < 128; e++) v += B1[e * PAD + t] * sv_s[e];
        sv_q[t] = v + 4096.0f * sv_tb[t];
    }
    __syncthreads();

    mg128(B0, B1, B2, t);          // T1 = G theta^T
    __syncthreads();

    for (int idx = t; idx < CI * CI; idx += 256) {
        int r = idx >> 7, c = idx & 127;
        B0[c * PAD + r] = phi_w[idx];
    }
    __syncthreads();
    if (t < CI) {
        float v = 0.f;
#pragma unroll 8
        for (int e = 0; e < 128; e++) v += B0[e * PAD + t] * sv_s[e];
        sv_u[t] = v;
    }
    __syncthreads();

    mg128(B0, B2, B1, t);          // L = phi T1
    __syncthreads();

    if (t < CI) {
        float w1 = sv_u[t];
        float w2 = phi_b[t];
        float* rowp = B1 + t * PAD;
        float mx = -1e30f;
#pragma unroll 8
        for (int d = 0; d < 128; d++) {
            float v = rowp[d] + w1 * sv_tb[d] + w2 * sv_q[d];
            rowp[d] = v;
            mx = fmaxf(mx, v);
        }
        float ssum = 0.f;
#pragma unroll 8
        for (int d = 0; d < 128; d++) {
            float ev = expf(rowp[d] - mx);
            rowp[d] = ev;
            ssum += ev;
        }
        float inv = 1.0f / ssum;
        float cacc = 0.f;
#pragma unroll 8
        for (int d = 0; d < 128; d++) {
            float f = rowp[d] * inv;
            B2[d * PAD + t] = f;
            cacc += f * sv_gb[d];
        }
        sv_c[t] = cacc;
    }
    __syncthreads();

    for (int idx = t; idx < CI * CI; idx += 256)
        B0[(idx >> 7) * PAD + (idx & 127)] = g_w[idx];
    __syncthreads();

    mg128(B2, B0, B1, t);          // M = f g_w
    __syncthreads();

    for (int idx = t; idx < CI * CI; idx += 256) {
        int r = idx >> 7, c = idx & 127;
        B2[c * PAD + r] = W_w[idx];
    }
    __syncthreads();

    if (t < CI) {
        float b0 = 0.f;
#pragma unroll 8
        for (int e = 0; e < 128; e++) b0 += B2[e * PAD + t] * sv_c[e];
        float sc = sv_scale[t];
        g_bvec[bb * CI + t] = sc * (b0 + W_b[t]) + bn_beta[t] - bn_mean[t] * sc;
    }

    mg128_final(B2, B1, g_Ah + (size_t)bb * CI * CI, g_Al + (size_t)bb * CI * CI,
                sv_scale, t);
}

// =====================================================================
// Kernel 3: Z = A'' X + b' via mma.sync tf32x3.
// grid (16, 64), 512 threads (16 warps -> 4/SMSP). CTA tile 128ch x 256px.
// A'' resident; X: 8 chunks of [16 ch x 256 px], double-buffered.
// Warp tile 32ch x 64px (m2 x n8). One barrier per chunk.
// =====================================================================
#define AP_XBUF (16 * XST)
#define AP_SMEM ((2 * 128 * ASTR + 4 * AP_XBUF) * 4)   // 202752 B

__global__ void __launch_bounds__(512)
apply_kernel(const float* __restrict__ X, float* __restrict__ Z)
{
    extern __shared__ float apsm[];
    float* sAh = apsm;                          // [128][ASTR]
    float* sAl = sAh + 128 * ASTR;
    float* sXh[2] = {sAl + 128 * ASTR, sAl + 128 * ASTR + AP_XBUF};
    float* sXl[2] = {sAl + 128 * ASTR + 2 * AP_XBUF,
                     sAl + 128 * ASTR + 3 * AP_XBUF};

    const int t = threadIdx.x;
    const int lane = t & 31, w = t >> 5;
    const int wr = (w >> 2) * 32;          // 4 ch-groups of 32
    const int wc = (w & 3) * 64;           // 4 px-groups of 64
    const int qr = lane >> 2, qc = lane & 3;
    const int bb = blockIdx.y;
    const int n0 = blockIdx.x * 256;

    // ---- stage A'' hi/lo resident (coalesced float4) ----
    {
        const int row = t >> 2, seg = (t & 3) * 32;
        const float* Ah = g_Ah + (size_t)bb * CI * CI + row * CI + seg;
        const float* Al = g_Al + (size_t)bb * CI * CI + row * CI + seg;
#pragma unroll
        for (int j = 0; j < 8; j++) {
            *(float4*)&sAh[row * ASTR + seg + 4 * j] = *(const float4*)(Ah + 4 * j);
            *(float4*)&sAl[row * ASTR + seg + 4 * j] = *(const float4*)(Al + 4 * j);
        }
    }

    float bias[2][2];
#pragma unroll
    for (int m = 0; m < 2; m++) {
        bias[m][0] = g_bvec[bb * CI + wr + m * 16 + qr];
        bias[m][1] = g_bvec[bb * CI + wr + m * 16 + qr + 8];
    }

    const float* Xb = X + (size_t)bb * CI * NPIX;
    float* Zb = Z + (size_t)bb * CI * NPIX;

    // X loader: warp w loads chunk-row w (16 rows per chunk), lane covers
    // px lane*4 and lane*4+128 (2x float4, coalesced 512B per warp).
    const int lch = w >> 0;   // 0..15
    const int lpx = lane * 4;

    float acc[2][8][4];
#pragma unroll
    for (int m = 0; m < 2; m++)
#pragma unroll
        for (int n = 0; n < 8; n++)
#pragma unroll
            for (int r = 0; r < 4; r++) acc[m][n][r] = 0.f;

    // preload chunk 0 (channels 0..15)
    {
        const float* src = Xb + (size_t)lch * NPIX + n0;
#pragma unroll
        for (int j = 0; j < 2; j++) {
            float4 v = *(const float4*)(src + lpx + j * 128);
            float h0, l0, h1, l1, h2, l2, h3, l3;
            tf32split(v.x, h0, l0); tf32split(v.y, h1, l1);
            tf32split(v.z, h2, l2); tf32split(v.w, h3, l3);
            *(float4*)&sXh[0][lch * XST + lpx + j * 128] = make_float4(h0, h1, h2, h3);
            *(float4*)&sXl[0][lch * XST + lpx + j * 128] = make_float4(l0, l1, l2, l3);
        }
    }
    __syncthreads();

    for (int g = 0; g < 8; g++) {
        const int b = g & 1;
        float4 nx[2];
        if (g < 7) {
            const float* src = Xb + (size_t)((g + 1) * 16 + lch) * NPIX + n0;
#pragma unroll
            for (int j = 0; j < 2; j++) nx[j] = *(const float4*)(src + lpx + j * 128);
        }

#pragma unroll
        for (int ks = 0; ks < 2; ks++) {
            const int kl = ks * 8;
            const int kg = g * 16 + kl;
            float Ahf[2][4], Alf[2][4];
#pragma unroll
            for (int m = 0; m < 2; m++) {
                const int ar = wr + m * 16 + qr;
                Ahf[m][0] = sAh[ar * ASTR + kg + qc];
                Ahf[m][1] = sAh[(ar + 8) * ASTR + kg + qc];
                Ahf[m][2] = sAh[ar * ASTR + kg + qc + 4];
                Ahf[m][3] = sAh[(ar + 8) * ASTR + kg + qc + 4];
                Alf[m][0] = sAl[ar * ASTR + kg + qc];
                Alf[m][1] = sAl[(ar + 8) * ASTR + kg + qc];
                Alf[m][2] = sAl[ar * ASTR + kg + qc + 4];
                Alf[m][3] = sAl[(ar + 8) * ASTR + kg + qc + 4];
            }
#pragma unroll
            for (int n = 0; n < 8; n++) {
                const int bpx = wc + n * 8 + qr;
                float Bh[2], Bl[2];
                Bh[0] = sXh[b][(kl + qc) * XST + bpx];
                Bh[1] = sXh[b][(kl + qc + 4) * XST + bpx];
                Bl[0] = sXl[b][(kl + qc) * XST + bpx];
                Bl[1] = sXl[b][(kl + qc + 4) * XST + bpx];
#pragma unroll
                for (int m = 0; m < 2; m++) {
                    mma8(acc[m][n], Ahf[m], Bh);
                    mma8(acc[m][n], Ahf[m], Bl);
                    mma8(acc[m][n], Alf[m], Bh);
                }
            }
        }

        if (g < 7) {
#pragma unroll
            for (int j = 0; j < 2; j++) {
                float4 v = nx[j];
                float h0, l0, h1, l1, h2, l2, h3, l3;
                tf32split(v.x, h0, l0); tf32split(v.y, h1, l1);
                tf32split(v.z, h2, l2); tf32split(v.w, h3, l3);
                *(float4*)&sXh[b ^ 1][lch * XST + lpx + j * 128] = make_float4(h0, h1, h2, h3);
                *(float4*)&sXl[b ^ 1][lch * XST + lpx + j * 128] = make_float4(l0, l1, l2, l3);
            }
        }
        __syncthreads();
    }

    // ---- epilogue: bias + store ----
#pragma unroll
    for (int m = 0; m < 2; m++) {
        const int r0 = wr + m * 16 + qr;
#pragma unroll
        for (int n = 0; n < 8; n++) {
            const int c0 = n0 + wc + n * 8 + qc * 2;
            *(float2*)(Zb + (size_t)r0 * NPIX + c0) =
                make_float2(acc[m][n][0] + bias[m][0], acc[m][n][1] + bias[m][0]);
            *(float2*)(Zb + (size_t)(r0 + 8) * NPIX + c0) =
                make_float2(acc[m][n][2] + bias[m][1], acc[m][n][3] + bias[m][1]);
        }
    }
}

// =====================================================================
extern "C" void kernel_launch(void* const* d_in, const int* in_sizes, int n_in,
                              void* d_out, int out_size)
{
    (void)in_sizes; (void)n_in; (void)out_size;
    const float* x        = (const float*)d_in[0];
    const float* theta_w  = (const float*)d_in[1];
    const float* theta_b  = (const float*)d_in[2];
    const float* phi_w    = (const float*)d_in[3];
    const float* phi_b    = (const float*)d_in[4];
    const float* g_w      = (const float*)d_in[5];
    const float* g_b      = (const float*)d_in[6];
    const float* W_w      = (const float*)d_in[7];
    const float* W_b      = (const float*)d_in[8];
    const float* bn_gamma = (const float*)d_in[9];
    const float* bn_beta  = (const float*)d_in[10];
    const float* bn_mean  = (const float*)d_in[11];
    const float* bn_var   = (const float*)d_in[12];
    float* out = (float*)d_out;

    const int smem_chain = 3 * CI * PAD * (int)sizeof(float);  // 202752
    cudaFuncSetAttribute(chain_kernel,
                         cudaFuncAttributeMaxDynamicSharedMemorySize, smem_chain);
    cudaFuncSetAttribute(apply_kernel,
                         cudaFuncAttributeMaxDynamicSharedMemorySize, AP_SMEM);

    gram_kernel<<<dim3(KSPLIT, NB), 256>>>(x);
    chain_kernel<<<NB, 256, smem_chain>>>(theta_w, theta_b, phi_w, phi_b,
                                          g_w, g_b, W_w, W_b,
                                          bn_gamma, bn_beta, bn_mean, bn_var);
    apply_kernel<<<dim3(NPIX / 256, NB), 512, AP_SMEM>>>(x, out);
}

// round 8
// speedup vs baseline: 1.1593x; 1.0482x over previous
#include <cuda_runtime.h>
#include <cuda_bf16.h>
#include <cstdint>
#include <math.h>

// Problem constants:
//  x: [16, 512, 64, 64] fp32 == [64 batches][128 ch][4096 px] contiguous
#define NB     64
#define CI     128
#define NPIX   4096
#define KSPLIT 8                 // gram K-split CTAs per batch (K=512 each)
#define PAD    132               // chain smem stride
#define GSTR   20                // gram smem stride (16 + 4)
#define ASTR   132               // apply A smem stride (conflict-free A frags)
#define XST    264               // apply X smem stride (264%32==8 -> conflict-free B frags)

// ---------------- tf32 helpers ----------------
__device__ __forceinline__ void tf32split(float v, float& h, float& l) {
    uint32_t hb;
    asm("cvt.rna.tf32.f32 %0, %1;" : "=r"(hb) : "f"(v));
    h = __uint_as_float(hb);
    float lr = v - h;
    uint32_t lb;
    asm("cvt.rna.tf32.f32 %0, %1;" : "=r"(lb) : "f"(lr));
    l = __uint_as_float(lb);
}

// D += A(16x8,row) * B(8x8,col)   tf32 x f32-accum
__device__ __forceinline__ void mma8(float* d, const float* a, const float* b) {
    asm volatile(
        "mma.sync.aligned.m16n8k8.row.col.f32.tf32.tf32.f32 "
        "{%0,%1,%2,%3}, {%4,%5,%6,%7}, {%8,%9}, {%0,%1,%2,%3};"
        : "+f"(d[0]), "+f"(d[1]), "+f"(d[2]), "+f"(d[3])
        : "r"(__float_as_uint(a[0])), "r"(__float_as_uint(a[1])),
          "r"(__float_as_uint(a[2])), "r"(__float_as_uint(a[3])),
          "r"(__float_as_uint(b[0])), "r"(__float_as_uint(b[1])));
}

// ---------------- scratch ----------------
__device__ float g_Gpart[NB * KSPLIT * CI * CI];   // partial E (G = (E+E^T)/2)
__device__ float g_spart[NB * KSPLIT * CI];        // partial row sums
__device__ float g_Ah[NB * CI * CI];               // A'' tf32-hi
__device__ float g_Al[NB * CI * CI];               // A'' tf32-lo
__device__ float g_bvec[NB * CI];                  // folded bias b'

// =====================================================================
// Kernel 1 (proven, 121us): partial E = H H^T + H (2L)^T.
// grid (KSPLIT, NB), 256 threads, 2 CTAs/SM. 32 chunks of 16 px.
// =====================================================================
__device__ __forceinline__ float gram_split(float4 v0, float4 v1,
                                            float* bH, float* bL, int lrow, int lseg)
{
    float va[8] = {v0.x, v0.y, v0.z, v0.w, v1.x, v1.y, v1.z, v1.w};
    float h[8], l[8];
#pragma unroll
    for (int j = 0; j < 8; j++) {
        tf32split(va[j], h[j], l[j]);
        l[j] *= 2.0f;
    }
    *(float4*)&bH[lrow * GSTR + lseg]     = make_float4(h[0], h[1], h[2], h[3]);
    *(float4*)&bH[lrow * GSTR + lseg + 4] = make_float4(h[4], h[5], h[6], h[7]);
    *(float4*)&bL[lrow * GSTR + lseg]     = make_float4(l[0], l[1], l[2], l[3]);
    *(float4*)&bL[lrow * GSTR + lseg + 4] = make_float4(l[4], l[5], l[6], l[7]);
    return va[0] + va[1] + va[2] + va[3] + va[4] + va[5] + va[6] + va[7];
}

__global__ void __launch_bounds__(256, 2)
gram_kernel(const float* __restrict__ X)
{
    __shared__ float sH[2][128 * GSTR];
    __shared__ float sL[2][128 * GSTR];
    __shared__ float sred[256];

    const int t = threadIdx.x;
    const int lane = t & 31, w = t >> 5;
    const int wr = (w >> 2) * 64, wc = (w & 3) * 32;
    const int qr = lane >> 2, qc = lane & 3;
    const int kc = blockIdx.x, bb = blockIdx.y;

    const float* Xb = X + (size_t)bb * CI * NPIX + (size_t)kc * 512;
    const int lrow = t >> 1, lseg = (t & 1) * 8;
    const float* Xr = Xb + (size_t)lrow * NPIX;

    float acc[4][4][4];
#pragma unroll
    for (int m = 0; m < 4; m++)
#pragma unroll
        for (int n = 0; n < 4; n++)
#pragma unroll
            for (int r = 0; r < 4; r++) acc[m][n][r] = 0.f;
    float mysum = 0.f;

    {
        float4 v0 = *(const float4*)(Xr + lseg);
        float4 v1 = *(const float4*)(Xr + lseg + 4);
        mysum += gram_split(v0, v1, sH[0], sL[0], lrow, lseg);
    }
    __syncthreads();

    for (int ch = 0; ch < 32; ch++) {
        const int b = ch & 1;
        float4 n0, n1;
        if (ch < 31) {
            n0 = *(const float4*)(Xr + (ch + 1) * 16 + lseg);
            n1 = *(const float4*)(Xr + (ch + 1) * 16 + lseg + 4);
        }

        const float* cH = sH[b];
        const float* cL = sL[b];
#pragma unroll
        for (int ks = 0; ks < 2; ks++) {
            const int k0 = ks * 8;
            float Ah[4][4];
#pragma unroll
            for (int m = 0; m < 4; m++) {
                const int ar = wr + m * 16 + qr;
                Ah[m][0] = cH[ar * GSTR + k0 + qc];
                Ah[m][1] = cH[(ar + 8) * GSTR + k0 + qc];
                Ah[m][2] = cH[ar * GSTR + k0 + qc + 4];
                Ah[m][3] = cH[(ar + 8) * GSTR + k0 + qc + 4];
            }
#pragma unroll
            for (int n = 0; n < 4; n++) {
                const int br = wc + n * 8 + qr;
                float Bh[2], Bl[2];
                Bh[0] = cH[br * GSTR + k0 + qc];
                Bh[1] = cH[br * GSTR + k0 + qc + 4];
                Bl[0] = cL[br * GSTR + k0 + qc];
                Bl[1] = cL[br * GSTR + k0 + qc + 4];
#pragma unroll
                for (int m = 0; m < 4; m++) {
                    mma8(acc[m][n], Ah[m], Bh);
                    mma8(acc[m][n], Ah[m], Bl);
                }
            }
        }

        if (ch < 31)
            mysum += gram_split(n0, n1, sH[b ^ 1], sL[b ^ 1], lrow, lseg);
        __syncthreads();
    }

    sred[t] = mysum;
    __syncthreads();
    if (t < 128)
        g_spart[(bb * KSPLIT + kc) * CI + t] = sred[2 * t] + sred[2 * t + 1];

    float* P = g_Gpart + ((size_t)(bb * KSPLIT + kc)) * CI * CI;
#pragma unroll
    for (int m = 0; m < 4; m++) {
        const int r0 = wr + m * 16 + qr;
#pragma unroll
        for (int n = 0; n < 4; n++) {
            const int c0 = wc + n * 8 + qc * 2;
            *(float2*)(P + (size_t)r0 * CI + c0)       = make_float2(acc[m][n][0], acc[m][n][1]);
            *(float2*)(P + (size_t)(r0 + 8) * CI + c0) = make_float2(acc[m][n][2], acc[m][n][3]);
        }
    }
}

// =====================================================================
// Kernel 2: chain (fp32 CUDA cores) + tf32 split of A''.  (proven path)
// =====================================================================
__device__ __forceinline__ void mg128(const float* U, const float* V, float* O, int t)
{
    const int tr = (t >> 4) << 3;
    const int tc = (t & 15) << 3;
    float acc[8][8];
#pragma unroll
    for (int i = 0; i < 8; i++)
#pragma unroll
        for (int j = 0; j < 8; j++) acc[i][j] = 0.f;
#pragma unroll 4
    for (int e = 0; e < 128; e++) {
        float4 a0 = *(const float4*)(U + e * PAD + tr);
        float4 a1 = *(const float4*)(U + e * PAD + tr + 4);
        float4 b0 = *(const float4*)(V + e * PAD + tc);
        float4 b1 = *(const float4*)(V + e * PAD + tc + 4);
        float a[8] = {a0.x, a0.y, a0.z, a0.w, a1.x, a1.y, a1.z, a1.w};
        float b[8] = {b0.x, b0.y, b0.z, b0.w, b1.x, b1.y, b1.z, b1.w};
#pragma unroll
        for (int i = 0; i < 8; i++)
#pragma unroll
            for (int j = 0; j < 8; j++) acc[i][j] += a[i] * b[j];
    }
#pragma unroll
    for (int i = 0; i < 8; i++)
#pragma unroll
        for (int j = 0; j < 8; j++)
            O[(tr + i) * PAD + (tc + j)] = acc[i][j];
}

__device__ __forceinline__ void mg128_final(const float* U, const float* V,
                                            float* gAh, float* gAl,
                                            const float* scale, int t)
{
    const int tr = (t >> 4) << 3;
    const int tc = (t & 15) << 3;
    float acc[8][8];
#pragma unroll
    for (int i = 0; i < 8; i++)
#pragma unroll
        for (int j = 0; j < 8; j++) acc[i][j] = 0.f;
#pragma unroll 4
    for (int e = 0; e < 128; e++) {
        float4 a0 = *(const float4*)(U + e * PAD + tr);
        float4 a1 = *(const float4*)(U + e * PAD + tr + 4);
        float4 b0 = *(const float4*)(V + e * PAD + tc);
        float4 b1 = *(const float4*)(V + e * PAD + tc + 4);
        float a[8] = {a0.x, a0.y, a0.z, a0.w, a1.x, a1.y, a1.z, a1.w};
        float b[8] = {b0.x, b0.y, b0.z, b0.w, b1.x, b1.y, b1.z, b1.w};
#pragma unroll
        for (int i = 0; i < 8; i++)
#pragma unroll
            for (int j = 0; j < 8; j++) acc[i][j] += a[i] * b[j];
    }
#pragma unroll
    for (int i = 0; i < 8; i++) {
        float sc = scale[tr + i];
#pragma unroll
        for (int j = 0; j < 8; j++) {
            int r = tr + i, c = tc + j;
            float val = sc * acc[i][j] + ((r == c) ? 1.0f : 0.0f);
            float h, l;
            tf32split(val, h, l);
            gAh[r * CI + c] = h;
            gAl[r * CI + c] = l;
        }
    }
}

__global__ void __launch_bounds__(256)
chain_kernel(const float* __restrict__ theta_w, const float* __restrict__ theta_b,
             const float* __restrict__ phi_w,   const float* __restrict__ phi_b,
             const float* __restrict__ g_w,     const float* __restrict__ g_b,
             const float* __restrict__ W_w,     const float* __restrict__ W_b,
             const float* __restrict__ bn_gamma, const float* __restrict__ bn_beta,
             const float* __restrict__ bn_mean,  const float* __restrict__ bn_var)
{
    extern __shared__ float dsm[];
    float* B0 = dsm;
    float* B1 = dsm + CI * PAD;
    float* B2 = dsm + 2 * CI * PAD;

    __shared__ float sv_s[CI], sv_u[CI], sv_q[CI], sv_tb[CI],
                     sv_gb[CI], sv_c[CI], sv_scale[CI];

    const int t  = threadIdx.x;
    const int bb = blockIdx.x;

    const float* Gp = g_Gpart + (size_t)bb * KSPLIT * CI * CI;
    for (int idx = t; idx < CI * CI; idx += 256) {
        float v = 0.f;
#pragma unroll
        for (int ks = 0; ks < KSPLIT; ks++) v += Gp[ks * CI * CI + idx];
        B2[(idx >> 7) * PAD + (idx & 127)] = v;
    }
    if (t < CI) {
        float v = 0.f;
#pragma unroll
        for (int ks = 0; ks < KSPLIT; ks++) v += g_spart[(bb * KSPLIT + ks) * CI + t];
        sv_s[t]  = v;
        sv_tb[t] = theta_b[t];
        sv_gb[t] = g_b[t];
        sv_scale[t] = bn_gamma[t] * rsqrtf(bn_var[t] + 1e-5f);
    }
    for (int idx = t; idx < CI * CI; idx += 256) {
        int r = idx >> 7, c = idx & 127;
        B1[c * PAD + r] = theta_w[idx];
    }
    __syncthreads();

    // symmetrize: G = (S + S^T)/2 into B0;  q from theta^T
    for (int idx = t; idx < CI * CI; idx += 256) {
        int r = idx >> 7, c = idx & 127;
        B0[r * PAD + c] = 0.5f * (B2[r * PAD + c] + B2[c * PAD + r]);
    }
    if (t < CI) {
        float v = 0.f;
#pragma unroll 8
        for (int e = 0; e < 128; e++) v += B1[e * PAD + t] * sv_s[e];
        sv_q[t] = v + 4096.0f * sv_tb[t];
    }
    __syncthreads();

    mg128(B0, B1, B2, t);          // T1 = G theta^T
    __syncthreads();

    for (int idx = t; idx < CI * CI; idx += 256) {
        int r = idx >> 7, c = idx & 127;
        B0[c * PAD + r] = phi_w[idx];
    }
    __syncthreads();
    if (t < CI) {
        float v = 0.f;
#pragma unroll 8
        for (int e = 0; e < 128; e++) v += B0[e * PAD + t] * sv_s[e];
        sv_u[t] = v;
    }
    __syncthreads();

    mg128(B0, B2, B1, t);          // L = phi T1
    __syncthreads();

    if (t < CI) {
        float w1 = sv_u[t];
        float w2 = phi_b[t];
        float* rowp = B1 + t * PAD;
        float mx = -1e30f;
#pragma unroll 8
        for (int d = 0; d < 128; d++) {
            float v = rowp[d] + w1 * sv_tb[d] + w2 * sv_q[d];
            rowp[d] = v;
            mx = fmaxf(mx, v);
        }
        float ssum = 0.f;
#pragma unroll 8
        for (int d = 0; d < 128; d++) {
            float ev = expf(rowp[d] - mx);
            rowp[d] = ev;
            ssum += ev;
        }
        float inv = 1.0f / ssum;
        float cacc = 0.f;
#pragma unroll 8
        for (int d = 0; d < 128; d++) {
            float f = rowp[d] * inv;
            B2[d * PAD + t] = f;
            cacc += f * sv_gb[d];
        }
        sv_c[t] = cacc;
    }
    __syncthreads();

    for (int idx = t; idx < CI * CI; idx += 256)
        B0[(idx >> 7) * PAD + (idx & 127)] = g_w[idx];
    __syncthreads();

    mg128(B2, B0, B1, t);          // M = f g_w
    __syncthreads();

    for (int idx = t; idx < CI * CI; idx += 256) {
        int r = idx >> 7, c = idx & 127;
        B2[c * PAD + r] = W_w[idx];
    }
    __syncthreads();

    if (t < CI) {
        float b0 = 0.f;
#pragma unroll 8
        for (int e = 0; e < 128; e++) b0 += B2[e * PAD + t] * sv_c[e];
        float sc = sv_scale[t];
        g_bvec[bb * CI + t] = sc * (b0 + W_b[t]) + bn_beta[t] - bn_mean[t] * sc;
    }

    mg128_final(B2, B1, g_Ah + (size_t)bb * CI * CI, g_Al + (size_t)bb * CI * CI,
                sv_scale, t);
}

// =====================================================================
// Kernel 3: Z = A'' X + b' via mma.sync tf32x3, SINGLE-WAVE persistent.
// grid (2, 64) = 128 CTAs, 512 threads. Each CTA: one batch-half (2048 px).
// A'' staged once; 64 flattened chunks (8 px-subtiles x 8 k-chunks of
// [16ch x 256px]), double-buffered, 1 barrier/chunk, epilogue every 8th.
// =====================================================================
#define AP_XBUF (16 * XST)
#define AP_SMEM ((2 * 128 * ASTR + 4 * AP_XBUF) * 4)   // 202752 B

__global__ void __launch_bounds__(512)
apply_kernel(const float* __restrict__ X, float* __restrict__ Z)
{
    extern __shared__ float apsm[];
    float* sAh = apsm;                          // [128][ASTR]
    float* sAl = sAh + 128 * ASTR;
    float* sXh[2] = {sAl + 128 * ASTR, sAl + 128 * ASTR + AP_XBUF};
    float* sXl[2] = {sAl + 128 * ASTR + 2 * AP_XBUF,
                     sAl + 128 * ASTR + 3 * AP_XBUF};

    const int t = threadIdx.x;
    const int lane = t & 31, w = t >> 5;
    const int wr = (w >> 2) * 32;          // 4 ch-groups of 32
    const int wc = (w & 3) * 64;           // 4 px-groups of 64
    const int qr = lane >> 2, qc = lane & 3;
    const int bb = blockIdx.y;
    const int half0 = blockIdx.x * 2048;   // this CTA's px range start

    // ---- stage A'' hi/lo resident ONCE ----
    {
        const int row = t >> 2, seg = (t & 3) * 32;
        const float* Ah = g_Ah + (size_t)bb * CI * CI + row * CI + seg;
        const float* Al = g_Al + (size_t)bb * CI * CI + row * CI + seg;
#pragma unroll
        for (int j = 0; j < 8; j++) {
            *(float4*)&sAh[row * ASTR + seg + 4 * j] = *(const float4*)(Ah + 4 * j);
            *(float4*)&sAl[row * ASTR + seg + 4 * j] = *(const float4*)(Al + 4 * j);
        }
    }

    float bias[2][2];
#pragma unroll
    for (int m = 0; m < 2; m++) {
        bias[m][0] = g_bvec[bb * CI + wr + m * 16 + qr];
        bias[m][1] = g_bvec[bb * CI + wr + m * 16 + qr + 8];
    }

    const float* Xb = X + (size_t)bb * CI * NPIX;
    float* Zb = Z + (size_t)bb * CI * NPIX;

    const int lch = w;          // loader: warp w -> chunk-row w (16 rows/chunk)
    const int lpx = lane * 4;

    float acc[2][8][4];
#pragma unroll
    for (int m = 0; m < 2; m++)
#pragma unroll
        for (int n = 0; n < 8; n++)
#pragma unroll
            for (int r = 0; r < 4; r++) acc[m][n][r] = 0.f;

    // preload chunk 0 (subtile 0, channels 0..15)
    {
        const float* src = Xb + (size_t)lch * NPIX + half0;
#pragma unroll
        for (int j = 0; j < 2; j++) {
            float4 v = *(const float4*)(src + lpx + j * 128);
            float h0, l0, h1, l1, h2, l2, h3, l3;
            tf32split(v.x, h0, l0); tf32split(v.y, h1, l1);
            tf32split(v.z, h2, l2); tf32split(v.w, h3, l3);
            *(float4*)&sXh[0][lch * XST + lpx + j * 128] = make_float4(h0, h1, h2, h3);
            *(float4*)&sXl[0][lch * XST + lpx + j * 128] = make_float4(l0, l1, l2, l3);
        }
    }
    __syncthreads();

    // 64 flattened chunks: c -> subtile s = c>>3 (px), k-chunk g = c&7 (ch)
    for (int c = 0; c < 64; c++) {
        const int b = c & 1;
        const int g = c & 7;

        float4 nx[2];
        if (c < 63) {
            const int ng = (c + 1) & 7, ns = (c + 1) >> 3;
            const float* src = Xb + (size_t)(ng * 16 + lch) * NPIX + half0 + ns * 256;
#pragma unroll
            for (int j = 0; j < 2; j++) nx[j] = *(const float4*)(src + lpx + j * 128);
        }

#pragma unroll
        for (int ks = 0; ks < 2; ks++) {
            const int kl = ks * 8;
            const int kg = g * 16 + kl;
            float Ahf[2][4], Alf[2][4];
#pragma unroll
            for (int m = 0; m < 2; m++) {
                const int ar = wr + m * 16 + qr;
                Ahf[m][0] = sAh[ar * ASTR + kg + qc];
                Ahf[m][1] = sAh[(ar + 8) * ASTR + kg + qc];
                Ahf[m][2] = sAh[ar * ASTR + kg + qc + 4];
                Ahf[m][3] = sAh[(ar + 8) * ASTR + kg + qc + 4];
                Alf[m][0] = sAl[ar * ASTR + kg + qc];
                Alf[m][1] = sAl[(ar + 8) * ASTR + kg + qc];
                Alf[m][2] = sAl[ar * ASTR + kg + qc + 4];
                Alf[m][3] = sAl[(ar + 8) * ASTR + kg + qc + 4];
            }
#pragma unroll
            for (int n = 0; n < 8; n++) {
                const int bpx = wc + n * 8 + qr;
                float Bh[2], Bl[2];
                Bh[0] = sXh[b][(kl + qc) * XST + bpx];
                Bh[1] = sXh[b][(kl + qc + 4) * XST + bpx];
                Bl[0] = sXl[b][(kl + qc) * XST + bpx];
                Bl[1] = sXl[b][(kl + qc + 4) * XST + bpx];
#pragma unroll
                for (int m = 0; m < 2; m++) {
                    mma8(acc[m][n], Ahf[m], Bh);
                    mma8(acc[m][n], Ahf[m], Bl);
                    mma8(acc[m][n], Alf[m], Bh);
                }
            }
        }

        if (c < 63) {
#pragma unroll
            for (int j = 0; j < 2; j++) {
                float4 v = nx[j];
                float h0, l0, h1, l1, h2, l2, h3, l3;
                tf32split(v.x, h0, l0); tf32split(v.y, h1, l1);
                tf32split(v.z, h2, l2); tf32split(v.w, h3, l3);
                *(float4*)&sXh[b ^ 1][lch * XST + lpx + j * 128] = make_float4(h0, h1, h2, h3);
                *(float4*)&sXl[b ^ 1][lch * XST + lpx + j * 128] = make_float4(l0, l1, l2, l3);
            }
        }
        __syncthreads();

        // epilogue at end of each px-subtile
        if (g == 7) {
            const int px0 = half0 + (c >> 3) * 256;
#pragma unroll
            for (int m = 0; m < 2; m++) {
                const int r0 = wr + m * 16 + qr;
#pragma unroll
                for (int n = 0; n < 8; n++) {
                    const int c0 = px0 + wc + n * 8 + qc * 2;
                    *(float2*)(Zb + (size_t)r0 * NPIX + c0) =
                        make_float2(acc[m][n][0] + bias[m][0], acc[m][n][1] + bias[m][0]);
                    *(float2*)(Zb + (size_t)(r0 + 8) * NPIX + c0) =
                        make_float2(acc[m][n][2] + bias[m][1], acc[m][n][3] + bias[m][1]);
                }
            }
#pragma unroll
            for (int m = 0; m < 2; m++)
#pragma unroll
                for (int n = 0; n < 8; n++)
#pragma unroll
                    for (int r = 0; r < 4; r++) acc[m][n][r] = 0.f;
        }
    }
}

// =====================================================================
extern "C" void kernel_launch(void* const* d_in, const int* in_sizes, int n_in,
                              void* d_out, int out_size)
{
    (void)in_sizes; (void)n_in; (void)out_size;
    const float* x        = (const float*)d_in[0];
    const float* theta_w  = (const float*)d_in[1];
    const float* theta_b  = (const float*)d_in[2];
    const float* phi_w    = (const float*)d_in[3];
    const float* phi_b    = (const float*)d_in[4];
    const float* g_w      = (const float*)d_in[5];
    const float* g_b      = (const float*)d_in[6];
    const float* W_w      = (const float*)d_in[7];
    const float* W_b      = (const float*)d_in[8];
    const float* bn_gamma = (const float*)d_in[9];
    const float* bn_beta  = (const float*)d_in[10];
    const float* bn_mean  = (const float*)d_in[11];
    const float* bn_var   = (const float*)d_in[12];
    float* out = (float*)d_out;

    const int smem_chain = 3 * CI * PAD * (int)sizeof(float);  // 202752
    cudaFuncSetAttribute(chain_kernel,
                         cudaFuncAttributeMaxDynamicSharedMemorySize, smem_chain);
    cudaFuncSetAttribute(apply_kernel,
                         cudaFuncAttributeMaxDynamicSharedMemorySize, AP_SMEM);

    gram_kernel<<<dim3(KSPLIT, NB), 256>>>(x);
    chain_kernel<<<NB, 256, smem_chain>>>(theta_w, theta_b, phi_w, phi_b,
                                          g_w, g_b, W_w, W_b,
                                          bn_gamma, bn_beta, bn_mean, bn_var);
    apply_kernel<<<dim3(2, NB), 512, AP_SMEM>>>(x, out);
}

// round 9
// speedup vs baseline: 1.7704x; 1.5272x over previous
#include <cuda_runtime.h>
#include <cuda_fp16.h>
#include <cstdint>
#include <math.h>

// Problem constants:
//  x: [16, 512, 64, 64] fp32 == [64 batches][128 ch][4096 px] contiguous
#define NB     64
#define CI     128
#define NPIX   4096
#define KSPLIT 8                 // gram K-split CTAs per batch (K=512 each)
#define PAD    132               // chain smem stride
#define GPR    12                // gram pair stride (8 pairs + 4)
#define APR    68                // apply A pair stride (64 pairs + 4)
#define XPR    264               // apply X pair stride (256 px + 8)

// ---------------- fp16 helpers ----------------
__device__ __forceinline__ unsigned h2pack(__half a, __half b) {
    __half2 v = __halves2half2(a, b);
    return *(unsigned*)&v;
}
// split v = h + l (h,l fp16; l optionally pre-scaled)
__device__ __forceinline__ void f16split(float v, __half& h, float& lres) {
    h = __float2half_rn(v);
    lres = v - __half2float(h);
}

// D += A(16x16,row,f16) * B(16x8,col,f16)  fp32-accum
__device__ __forceinline__ void mmah(float* d, const unsigned* a, const unsigned* b) {
    asm volatile(
        "mma.sync.aligned.m16n8k16.row.col.f32.f16.f16.f32 "
        "{%0,%1,%2,%3}, {%4,%5,%6,%7}, {%8,%9}, {%0,%1,%2,%3};"
        : "+f"(d[0]), "+f"(d[1]), "+f"(d[2]), "+f"(d[3])
        : "r"(a[0]), "r"(a[1]), "r"(a[2]), "r"(a[3]), "r"(b[0]), "r"(b[1]));
}

// ---------------- scratch ----------------
__device__ float    g_Gpart[NB * KSPLIT * CI * CI]; // partial E (G = (E+E^T)/2)
__device__ float    g_spart[NB * KSPLIT * CI];      // partial row sums
__device__ unsigned g_Ah2[NB * CI * 64];            // A'' fp16-hi, half2-packed pairs
__device__ unsigned g_Al2[NB * CI * 64];            // A'' fp16-lo, half2-packed pairs
__device__ float    g_bvec[NB * CI];                // folded bias b'

// =====================================================================
// Kernel 1: partial E = H H^T + H (2L)^T via fp16 m16n8k16 (2 products).
// grid (KSPLIT, NB), 256 threads, 2 CTAs/SM. 32 chunks of 16 px
// (= exactly one k16 step), double-buffered, one barrier per chunk.
// smem layout: [ch row][px-pair] half2, stride GPR.
// =====================================================================
__device__ __forceinline__ float gram_cvt(const float* __restrict__ src,
                                          unsigned* bH, unsigned* bL, int base)
{
    float4 v0 = *(const float4*)(src);
    float4 v1 = *(const float4*)(src + 4);
    float va[8] = {v0.x, v0.y, v0.z, v0.w, v1.x, v1.y, v1.z, v1.w};
    unsigned hu[4], lu[4];
    float sum = 0.f;
#pragma unroll
    for (int p = 0; p < 4; p++) {
        float a = va[2 * p], b = va[2 * p + 1];
        __half ha, hb; float la, lb;
        f16split(a, ha, la);
        f16split(b, hb, lb);
        hu[p] = h2pack(ha, hb);
        lu[p] = h2pack(__float2half_rn(la * 2.0f), __float2half_rn(lb * 2.0f));
        sum += a + b;
    }
    *(uint4*)&bH[base] = make_uint4(hu[0], hu[1], hu[2], hu[3]);
    *(uint4*)&bL[base] = make_uint4(lu[0], lu[1], lu[2], lu[3]);
    return sum;
}

__global__ void __launch_bounds__(256, 2)
gram_kernel(const float* __restrict__ X)
{
    __shared__ unsigned sH[2][128 * GPR];
    __shared__ unsigned sL[2][128 * GPR];
    __shared__ float sred[256];

    const int t = threadIdx.x;
    const int lane = t & 31, w = t >> 5;
    const int wr = (w >> 2) * 64, wc = (w & 3) * 32;
    const int qr = lane >> 2, qc = lane & 3;
    const int kc = blockIdx.x, bb = blockIdx.y;

    const float* Xb = X + (size_t)bb * CI * NPIX + (size_t)kc * 512;
    const int lrow = t >> 1, lp4 = (t & 1) * 4;      // pair offset 0/4, px offset lp4*2
    const int sbase = lrow * GPR + lp4;
    const float* Xr = Xb + (size_t)lrow * NPIX + lp4 * 2;

    float acc[4][4][4];
#pragma unroll
    for (int m = 0; m < 4; m++)
#pragma unroll
        for (int n = 0; n < 4; n++)
#pragma unroll
            for (int r = 0; r < 4; r++) acc[m][n][r] = 0.f;
    float mysum = 0.f;

    mysum += gram_cvt(Xr, sH[0], sL[0], sbase);
    __syncthreads();

    for (int ch = 0; ch < 32; ch++) {
        const int b = ch & 1;
        float4 n0, n1;
        if (ch < 31) {
            n0 = *(const float4*)(Xr + (ch + 1) * 16);
            n1 = *(const float4*)(Xr + (ch + 1) * 16 + 4);
        }

        const unsigned* cH = sH[b];
        const unsigned* cL = sL[b];
        // A fragments (shared by both products)
        unsigned Af[4][4];
#pragma unroll
        for (int m = 0; m < 4; m++) {
            const int ar = wr + m * 16 + qr;
            Af[m][0] = cH[ar * GPR + qc];
            Af[m][1] = cH[(ar + 8) * GPR + qc];
            Af[m][2] = cH[ar * GPR + qc + 4];
            Af[m][3] = cH[(ar + 8) * GPR + qc + 4];
        }
#pragma unroll
        for (int n = 0; n < 4; n++) {
            const int br = wc + n * 8 + qr;
            unsigned Bh[2] = {cH[br * GPR + qc], cH[br * GPR + qc + 4]};
            unsigned Bl[2] = {cL[br * GPR + qc], cL[br * GPR + qc + 4]};
#pragma unroll
            for (int m = 0; m < 4; m++) {
                mmah(acc[m][n], Af[m], Bh);
                mmah(acc[m][n], Af[m], Bl);
            }
        }

        if (ch < 31) {
            float va[8] = {n0.x, n0.y, n0.z, n0.w, n1.x, n1.y, n1.z, n1.w};
            unsigned hu[4], lu[4];
#pragma unroll
            for (int p = 0; p < 4; p++) {
                float a = va[2 * p], bv = va[2 * p + 1];
                __half ha, hb; float la, lb;
                f16split(a, ha, la);
                f16split(bv, hb, lb);
                hu[p] = h2pack(ha, hb);
                lu[p] = h2pack(__float2half_rn(la * 2.0f), __float2half_rn(lb * 2.0f));
                mysum += a + bv;
            }
            *(uint4*)&sH[b ^ 1][sbase] = make_uint4(hu[0], hu[1], hu[2], hu[3]);
            *(uint4*)&sL[b ^ 1][sbase] = make_uint4(lu[0], lu[1], lu[2], lu[3]);
        }
        __syncthreads();
    }

    sred[t] = mysum;
    __syncthreads();
    if (t < 128)
        g_spart[(bb * KSPLIT + kc) * CI + t] = sred[2 * t] + sred[2 * t + 1];

    float* P = g_Gpart + ((size_t)(bb * KSPLIT + kc)) * CI * CI;
#pragma unroll
    for (int m = 0; m < 4; m++) {
        const int r0 = wr + m * 16 + qr;
#pragma unroll
        for (int n = 0; n < 4; n++) {
            const int c0 = wc + n * 8 + qc * 2;
            *(float2*)(P + (size_t)r0 * CI + c0)       = make_float2(acc[m][n][0], acc[m][n][1]);
            *(float2*)(P + (size_t)(r0 + 8) * CI + c0) = make_float2(acc[m][n][2], acc[m][n][3]);
        }
    }
}

// =====================================================================
// Kernel 2: chain (fp32 CUDA cores, proven) + fp16 split of A''.
// =====================================================================
__device__ __forceinline__ void mg128(const float* U, const float* V, float* O, int t)
{
    const int tr = (t >> 4) << 3;
    const int tc = (t & 15) << 3;
    float acc[8][8];
#pragma unroll
    for (int i = 0; i < 8; i++)
#pragma unroll
        for (int j = 0; j < 8; j++) acc[i][j] = 0.f;
#pragma unroll 4
    for (int e = 0; e < 128; e++) {
        float4 a0 = *(const float4*)(U + e * PAD + tr);
        float4 a1 = *(const float4*)(U + e * PAD + tr + 4);
        float4 b0 = *(const float4*)(V + e * PAD + tc);
        float4 b1 = *(const float4*)(V + e * PAD + tc + 4);
        float a[8] = {a0.x, a0.y, a0.z, a0.w, a1.x, a1.y, a1.z, a1.w};
        float b[8] = {b0.x, b0.y, b0.z, b0.w, b1.x, b1.y, b1.z, b1.w};
#pragma unroll
        for (int i = 0; i < 8; i++)
#pragma unroll
            for (int j = 0; j < 8; j++) acc[i][j] += a[i] * b[j];
    }
#pragma unroll
    for (int i = 0; i < 8; i++)
#pragma unroll
        for (int j = 0; j < 8; j++)
            O[(tr + i) * PAD + (tc + j)] = acc[i][j];
}

__device__ __forceinline__ void mg128_final(const float* U, const float* V,
                                            unsigned* gAh, unsigned* gAl,
                                            const float* scale, int t)
{
    const int tr = (t >> 4) << 3;
    const int tc = (t & 15) << 3;
    float acc[8][8];
#pragma unroll
    for (int i = 0; i < 8; i++)
#pragma unroll
        for (int j = 0; j < 8; j++) acc[i][j] = 0.f;
#pragma unroll 4
    for (int e = 0; e < 128; e++) {
        float4 a0 = *(const float4*)(U + e * PAD + tr);
        float4 a1 = *(const float4*)(U + e * PAD + tr + 4);
        float4 b0 = *(const float4*)(V + e * PAD + tc);
        float4 b1 = *(const float4*)(V + e * PAD + tc + 4);
        float a[8] = {a0.x, a0.y, a0.z, a0.w, a1.x, a1.y, a1.z, a1.w};
        float b[8] = {b0.x, b0.y, b0.z, b0.w, b1.x, b1.y, b1.z, b1.w};
#pragma unroll
        for (int i = 0; i < 8; i++)
#pragma unroll
            for (int j = 0; j < 8; j++) acc[i][j] += a[i] * b[j];
    }
#pragma unroll
    for (int i = 0; i < 8; i++) {
        float sc = scale[tr + i];
        const int r = tr + i;
        float vals[8];
#pragma unroll
        for (int j = 0; j < 8; j++) {
            const int c = tc + j;
            vals[j] = sc * acc[i][j] + ((r == c) ? 1.0f : 0.0f);
        }
#pragma unroll
        for (int j = 0; j < 8; j += 2) {
            __half h0, h1; float l0, l1;
            f16split(vals[j], h0, l0);
            f16split(vals[j + 1], h1, l1);
            gAh[r * 64 + (tc + j) / 2] = h2pack(h0, h1);
            gAl[r * 64 + (tc + j) / 2] =
                h2pack(__float2half_rn(l0), __float2half_rn(l1));
        }
    }
}

__global__ void __launch_bounds__(256)
chain_kernel(const float* __restrict__ theta_w, const float* __restrict__ theta_b,
             const float* __restrict__ phi_w,   const float* __restrict__ phi_b,
             const float* __restrict__ g_w,     const float* __restrict__ g_b,
             const float* __restrict__ W_w,     const float* __restrict__ W_b,
             const float* __restrict__ bn_gamma, const float* __restrict__ bn_beta,
             const float* __restrict__ bn_mean,  const float* __restrict__ bn_var)
{
    extern __shared__ float dsm[];
    float* B0 = dsm;
    float* B1 = dsm + CI * PAD;
    float* B2 = dsm + 2 * CI * PAD;

    __shared__ float sv_s[CI], sv_u[CI], sv_q[CI], sv_tb[CI],
                     sv_gb[CI], sv_c[CI], sv_scale[CI];

    const int t  = threadIdx.x;
    const int bb = blockIdx.x;

    const float* Gp = g_Gpart + (size_t)bb * KSPLIT * CI * CI;
    for (int idx = t; idx < CI * CI; idx += 256) {
        float v = 0.f;
#pragma unroll
        for (int ks = 0; ks < KSPLIT; ks++) v += Gp[ks * CI * CI + idx];
        B2[(idx >> 7) * PAD + (idx & 127)] = v;
    }
    if (t < CI) {
        float v = 0.f;
#pragma unroll
        for (int ks = 0; ks < KSPLIT; ks++) v += g_spart[(bb * KSPLIT + ks) * CI + t];
        sv_s[t]  = v;
        sv_tb[t] = theta_b[t];
        sv_gb[t] = g_b[t];
        sv_scale[t] = bn_gamma[t] * rsqrtf(bn_var[t] + 1e-5f);
    }
    for (int idx = t; idx < CI * CI; idx += 256) {
        int r = idx >> 7, c = idx & 127;
        B1[c * PAD + r] = theta_w[idx];
    }
    __syncthreads();

    // symmetrize: G = (S + S^T)/2 into B0;  q from theta^T
    for (int idx = t; idx < CI * CI; idx += 256) {
        int r = idx >> 7, c = idx & 127;
        B0[r * PAD + c] = 0.5f * (B2[r * PAD + c] + B2[c * PAD + r]);
    }
    if (t < CI) {
        float v = 0.f;
#pragma unroll 8
        for (int e = 0; e < 128; e++) v += B1[e * PAD + t] * sv_s[e];
        sv_q[t] = v + 4096.0f * sv_tb[t];
    }
    __syncthreads();

    mg128(B0, B1, B2, t);          // T1 = G theta^T
    __syncthreads();

    for (int idx = t; idx < CI * CI; idx += 256) {
        int r = idx >> 7, c = idx & 127;
        B0[c * PAD + r] = phi_w[idx];
    }
    __syncthreads();
    if (t < CI) {
        float v = 0.f;
#pragma unroll 8
        for (int e = 0; e < 128; e++) v += B0[e * PAD + t] * sv_s[e];
        sv_u[t] = v;
    }
    __syncthreads();

    mg128(B0, B2, B1, t);          // L = phi T1
    __syncthreads();

    if (t < CI) {
        float w1 = sv_u[t];
        float w2 = phi_b[t];
        float* rowp = B1 + t * PAD;
        float mx = -1e30f;
#pragma unroll 8
        for (int d = 0; d < 128; d++) {
            float v = rowp[d] + w1 * sv_tb[d] + w2 * sv_q[d];
            rowp[d] = v;
            mx = fmaxf(mx, v);
        }
        float ssum = 0.f;
#pragma unroll 8
        for (int d = 0; d < 128; d++) {
            float ev = expf(rowp[d] - mx);
            rowp[d] = ev;
            ssum += ev;
        }
        float inv = 1.0f / ssum;
        float cacc = 0.f;
#pragma unroll 8
        for (int d = 0; d < 128; d++) {
            float f = rowp[d] * inv;
            B2[d * PAD + t] = f;
            cacc += f * sv_gb[d];
        }
        sv_c[t] = cacc;
    }
    __syncthreads();

    for (int idx = t; idx < CI * CI; idx += 256)
        B0[(idx >> 7) * PAD + (idx & 127)] = g_w[idx];
    __syncthreads();

    mg128(B2, B0, B1, t);          // M = f g_w
    __syncthreads();

    for (int idx = t; idx < CI * CI; idx += 256) {
        int r = idx >> 7, c = idx & 127;
        B2[c * PAD + r] = W_w[idx];
    }
    __syncthreads();

    if (t < CI) {
        float b0 = 0.f;
#pragma unroll 8
        for (int e = 0; e < 128; e++) b0 += B2[e * PAD + t] * sv_c[e];
        float sc = sv_scale[t];
        g_bvec[bb * CI + t] = sc * (b0 + W_b[t]) + bn_beta[t] - bn_mean[t] * sc;
    }

    mg128_final(B2, B1, g_Ah2 + (size_t)bb * CI * 64, g_Al2 + (size_t)bb * CI * 64,
                sv_scale, t);
}

// =====================================================================
// Kernel 3: Z = A'' X + b' via fp16 3-product m16n8k16, single wave.
// grid (2, 64) = 128 CTAs, 512 threads. A'' hi/lo resident (half2 pairs,
// stride APR). X chunks: [32 ch x 256 px] as ch-pair half2 [16][XPR],
// double-buffered. 32 flattened chunks (8 subtiles x 4 k-chunks).
// =====================================================================
#define AP_SMEM ((2 * 128 * APR + 4 * 16 * XPR) * 4)   // 137216 B

__global__ void __launch_bounds__(512)
apply_kernel(const float* __restrict__ X, float* __restrict__ Z)
{
    extern __shared__ unsigned apsm[];
    unsigned* sAh = apsm;                       // [128][APR]
    unsigned* sAl = sAh + 128 * APR;
    unsigned* sXh[2] = {sAl + 128 * APR, sAl + 128 * APR + 16 * XPR};
    unsigned* sXl[2] = {sAl + 128 * APR + 2 * 16 * XPR,
                        sAl + 128 * APR + 3 * 16 * XPR};

    const int t = threadIdx.x;
    const int lane = t & 31, w = t >> 5;
    const int wr = (w >> 2) * 32;          // 4 ch-groups of 32
    const int wc = (w & 3) * 64;           // 4 px-groups of 64
    const int qr = lane >> 2, qc = lane & 3;
    const int bb = blockIdx.y;
    const int half0 = blockIdx.x * 2048;

    // ---- stage A'' hi/lo resident ONCE (half2-packed) ----
    {
        const int row = t >> 2, seg = (t & 3) * 16;
        const uint4* Ah = (const uint4*)(g_Ah2 + ((size_t)bb * CI + row) * 64 + seg);
        const uint4* Al = (const uint4*)(g_Al2 + ((size_t)bb * CI + row) * 64 + seg);
#pragma unroll
        for (int j = 0; j < 4; j++) {
            *(uint4*)&sAh[row * APR + seg + 4 * j] = Ah[j];
            *(uint4*)&sAl[row * APR + seg + 4 * j] = Al[j];
        }
    }

    float bias[2][2];
#pragma unroll
    for (int m = 0; m < 2; m++) {
        bias[m][0] = g_bvec[bb * CI + wr + m * 16 + qr];
        bias[m][1] = g_bvec[bb * CI + wr + m * 16 + qr + 8];
    }

    const float* Xb = X + (size_t)bb * CI * NPIX;
    float* Zb = Z + (size_t)bb * CI * NPIX;

    const int lp = w;              // loader pair row 0..15 (ch 2lp, 2lp+1)
    const int lpx = lane * 8;      // 8 px per lane

    float acc[2][8][4];
#pragma unroll
    for (int m = 0; m < 2; m++)
#pragma unroll
        for (int n = 0; n < 8; n++)
#pragma unroll
            for (int r = 0; r < 4; r++) acc[m][n][r] = 0.f;

    // converter helper (inline): 16 floats -> 8 h-uints + 8 l-uints
    // preload chunk 0 (subtile 0, k-chunk 0: channels 0..31)
    {
        const float* se = Xb + (size_t)(2 * lp) * NPIX + half0 + lpx;
        const float* so = Xb + (size_t)(2 * lp + 1) * NPIX + half0 + lpx;
        float4 e0 = *(const float4*)(se), e1 = *(const float4*)(se + 4);
        float4 o0 = *(const float4*)(so), o1 = *(const float4*)(so + 4);
        float ev[8] = {e0.x, e0.y, e0.z, e0.w, e1.x, e1.y, e1.z, e1.w};
        float ov[8] = {o0.x, o0.y, o0.z, o0.w, o1.x, o1.y, o1.z, o1.w};
        unsigned hu[8], lu[8];
#pragma unroll
        for (int i = 0; i < 8; i++) {
            __half he, ho; float le, lo;
            f16split(ev[i], he, le);
            f16split(ov[i], ho, lo);
            hu[i] = h2pack(he, ho);
            lu[i] = h2pack(__float2half_rn(le), __float2half_rn(lo));
        }
        *(uint4*)&sXh[0][lp * XPR + lpx]     = make_uint4(hu[0], hu[1], hu[2], hu[3]);
        *(uint4*)&sXh[0][lp * XPR + lpx + 4] = make_uint4(hu[4], hu[5], hu[6], hu[7]);
        *(uint4*)&sXl[0][lp * XPR + lpx]     = make_uint4(lu[0], lu[1], lu[2], lu[3]);
        *(uint4*)&sXl[0][lp * XPR + lpx + 4] = make_uint4(lu[4], lu[5], lu[6], lu[7]);
    }
    __syncthreads();

    // 32 flattened chunks: c -> subtile s = c>>2 (px), k-chunk g = c&3 (32 ch)
    for (int c = 0; c < 32; c++) {
        const int b = c & 1;
        const int g = c & 3;

        float4 ne0, ne1, no0, no1;
        if (c < 31) {
            const int ng = (c + 1) & 3, ns = (c + 1) >> 2;
            const float* se = Xb + (size_t)(ng * 32 + 2 * lp) * NPIX + half0 + ns * 256 + lpx;
            const float* so = se + NPIX;
            ne0 = *(const float4*)(se); ne1 = *(const float4*)(se + 4);
            no0 = *(const float4*)(so); no1 = *(const float4*)(so + 4);
        }

#pragma unroll
        for (int ks = 0; ks < 2; ks++) {
            const int kp0 = ks * 8;              // pair base within chunk
            const int ga = g * 16 + kp0;         // global pair base in A
            unsigned Ahf[2][4], Alf[2][4];
#pragma unroll
            for (int m = 0; m < 2; m++) {
                const int ar = wr + m * 16 + qr;
                Ahf[m][0] = sAh[ar * APR + ga + qc];
                Ahf[m][1] = sAh[(ar + 8) * APR + ga + qc];
                Ahf[m][2] = sAh[ar * APR + ga + qc + 4];
                Ahf[m][3] = sAh[(ar + 8) * APR + ga + qc + 4];
                Alf[m][0] = sAl[ar * APR + ga + qc];
                Alf[m][1] = sAl[(ar + 8) * APR + ga + qc];
                Alf[m][2] = sAl[ar * APR + ga + qc + 4];
                Alf[m][3] = sAl[(ar + 8) * APR + ga + qc + 4];
            }
#pragma unroll
            for (int n = 0; n < 8; n++) {
                const int bpx = wc + n * 8 + qr;
                unsigned Bh[2] = {sXh[b][(kp0 + qc) * XPR + bpx],
                                  sXh[b][(kp0 + qc + 4) * XPR + bpx]};
                unsigned Bl[2] = {sXl[b][(kp0 + qc) * XPR + bpx],
                                  sXl[b][(kp0 + qc + 4) * XPR + bpx]};
#pragma unroll
                for (int m = 0; m < 2; m++) {
                    mmah(acc[m][n], Ahf[m], Bh);
                    mmah(acc[m][n], Ahf[m], Bl);
                    mmah(acc[m][n], Alf[m], Bh);
                }
            }
        }

        if (c < 31) {
            float ev[8] = {ne0.x, ne0.y, ne0.z, ne0.w, ne1.x, ne1.y, ne1.z, ne1.w};
            float ov[8] = {no0.x, no0.y, no0.z, no0.w, no1.x, no1.y, no1.z, no1.w};
            unsigned hu[8], lu[8];
#pragma unroll
            for (int i = 0; i < 8; i++) {
                __half he, ho; float le, lo;
                f16split(ev[i], he, le);
                f16split(ov[i], ho, lo);
                hu[i] = h2pack(he, ho);
                lu[i] = h2pack(__float2half_rn(le), __float2half_rn(lo));
            }
            unsigned* dh = &sXh[b ^ 1][lp * XPR + lpx];
            unsigned* dl = &sXl[b ^ 1][lp * XPR + lpx];
            *(uint4*)(dh)     = make_uint4(hu[0], hu[1], hu[2], hu[3]);
            *(uint4*)(dh + 4) = make_uint4(hu[4], hu[5], hu[6], hu[7]);
            *(uint4*)(dl)     = make_uint4(lu[0], lu[1], lu[2], lu[3]);
            *(uint4*)(dl + 4) = make_uint4(lu[4], lu[5], lu[6], lu[7]);
        }
        __syncthreads();

        if (g == 3) {   // end of px-subtile: epilogue
            const int px0 = half0 + (c >> 2) * 256;
#pragma unroll
            for (int m = 0; m < 2; m++) {
                const int r0 = wr + m * 16 + qr;
#pragma unroll
                for (int n = 0; n < 8; n++) {
                    const int c0 = px0 + wc + n * 8 + qc * 2;
                    *(float2*)(Zb + (size_t)r0 * NPIX + c0) =
                        make_float2(acc[m][n][0] + bias[m][0], acc[m][n][1] + bias[m][0]);
                    *(float2*)(Zb + (size_t)(r0 + 8) * NPIX + c0) =
                        make_float2(acc[m][n][2] + bias[m][1], acc[m][n][3] + bias[m][1]);
                }
            }
#pragma unroll
            for (int m = 0; m < 2; m++)
#pragma unroll
                for (int n = 0; n < 8; n++)
#pragma unroll
                    for (int r = 0; r < 4; r++) acc[m][n][r] = 0.f;
        }
    }
}

// =====================================================================
extern "C" void kernel_launch(void* const* d_in, const int* in_sizes, int n_in,
                              void* d_out, int out_size)
{
    (void)in_sizes; (void)n_in; (void)out_size;
    const float* x        = (const float*)d_in[0];
    const float* theta_w  = (const float*)d_in[1];
    const float* theta_b  = (const float*)d_in[2];
    const float* phi_w    = (const float*)d_in[3];
    const float* phi_b    = (const float*)d_in[4];
    const float* g_w      = (const float*)d_in[5];
    const float* g_b      = (const float*)d_in[6];
    const float* W_w      = (const float*)d_in[7];
    const float* W_b      = (const float*)d_in[8];
    const float* bn_gamma = (const float*)d_in[9];
    const float* bn_beta  = (const float*)d_in[10];
    const float* bn_mean  = (const float*)d_in[11];
    const float* bn_var   = (const float*)d_in[12];
    float* out = (float*)d_out;

    const int smem_chain = 3 * CI * PAD * (int)sizeof(float);  // 202752
    cudaFuncSetAttribute(chain_kernel,
                         cudaFuncAttributeMaxDynamicSharedMemorySize, smem_chain);
    cudaFuncSetAttribute(apply_kernel,
                         cudaFuncAttributeMaxDynamicSharedMemorySize, AP_SMEM);

    gram_kernel<<<dim3(KSPLIT, NB), 256>>>(x);
    chain_kernel<<<NB, 256, smem_chain>>>(theta_w, theta_b, phi_w, phi_b,
                                          g_w, g_b, W_w, W_b,
                                          bn_gamma, bn_beta, bn_mean, bn_var);
    apply_kernel<<<dim3(2, NB), 512, AP_SMEM>>>(x, out);
}

// round 10
// speedup vs baseline: 2.0438x; 1.1544x over previous
#include <cuda_runtime.h>
#include <cuda_fp16.h>
#include <cstdint>
#include <math.h>

// Problem constants:
//  x: [16, 512, 64, 64] fp32 == [64 batches][128 ch][4096 px] contiguous
#define NB     64
#define CI     128
#define NPIX   4096
#define KSPLIT 8                 // gram K-split CTAs per batch (K=512 each)
#define GPR    12                // gram pair stride (8 pairs + 4)
#define APR    68                // packed pair stride (64 pairs + 4) - frag conflict-free
#define XPR    264               // apply X pair stride (256 px + 8)
#define F32S   132               // chain fp32 scratch stride

// ---------------- fp16 helpers ----------------
// paired split: (a,b) -> half2 hi + half2 lo  (lo optionally scaled)
__device__ __forceinline__ void split2(float a, float b, unsigned& hu, unsigned& lu) {
    __half2 h2 = __float22half2_rn(make_float2(a, b));
    float2 hf = __half22float2(h2);
    __half2 l2 = __float22half2_rn(make_float2(a - hf.x, b - hf.y));
    hu = *(unsigned*)&h2;
    lu = *(unsigned*)&l2;
}
__device__ __forceinline__ void split2s2(float a, float b, unsigned& hu, unsigned& lu) {
    __half2 h2 = __float22half2_rn(make_float2(a, b));
    float2 hf = __half22float2(h2);
    __half2 l2 = __float22half2_rn(make_float2((a - hf.x) * 2.0f, (b - hf.y) * 2.0f));
    hu = *(unsigned*)&h2;
    lu = *(unsigned*)&l2;
}

// D += A(16x16,row,f16) * B(16x8,col,f16)  fp32-accum
__device__ __forceinline__ void mmah(float* d, const unsigned* a, const unsigned* b) {
    asm volatile(
        "mma.sync.aligned.m16n8k16.row.col.f32.f16.f16.f32 "
        "{%0,%1,%2,%3}, {%4,%5,%6,%7}, {%8,%9}, {%0,%1,%2,%3};"
        : "+f"(d[0]), "+f"(d[1]), "+f"(d[2]), "+f"(d[3])
        : "r"(a[0]), "r"(a[1]), "r"(a[2]), "r"(a[3]), "r"(b[0]), "r"(b[1]));
}

// ---------------- scratch ----------------
__device__ float    g_Gpart[NB * KSPLIT * CI * CI]; // partial E (G = (E+E^T)/2)
__device__ float    g_spart[NB * KSPLIT * CI];      // partial row sums
__device__ unsigned g_Ah2[NB * CI * 64];            // A'' fp16-hi, half2 pairs
__device__ unsigned g_Al2[NB * CI * 64];            // A'' fp16-lo, half2 pairs
__device__ float    g_bvec[NB * CI];                // folded bias b'

// =====================================================================
// Kernel 1: partial E = H H^T + H (2L)^T via fp16 m16n8k16 (2 products).
// =====================================================================
__global__ void __launch_bounds__(256, 2)
gram_kernel(const float* __restrict__ X)
{
    __shared__ unsigned sH[2][128 * GPR];
    __shared__ unsigned sL[2][128 * GPR];
    __shared__ float sred[256];

    const int t = threadIdx.x;
    const int lane = t & 31, w = t >> 5;
    const int wr = (w >> 2) * 64, wc = (w & 3) * 32;
    const int qr = lane >> 2, qc = lane & 3;
    const int kc = blockIdx.x, bb = blockIdx.y;

    const float* Xb = X + (size_t)bb * CI * NPIX + (size_t)kc * 512;
    const int lrow = t >> 1, lp4 = (t & 1) * 4;
    const int sbase = lrow * GPR + lp4;
    const float* Xr = Xb + (size_t)lrow * NPIX + lp4 * 2;

    float acc[4][4][4];
#pragma unroll
    for (int m = 0; m < 4; m++)
#pragma unroll
        for (int n = 0; n < 4; n++)
#pragma unroll
            for (int r = 0; r < 4; r++) acc[m][n][r] = 0.f;
    float mysum = 0.f;

    {
        float4 v0 = *(const float4*)(Xr);
        float4 v1 = *(const float4*)(Xr + 4);
        unsigned hu[4], lu[4];
        split2s2(v0.x, v0.y, hu[0], lu[0]);
        split2s2(v0.z, v0.w, hu[1], lu[1]);
        split2s2(v1.x, v1.y, hu[2], lu[2]);
        split2s2(v1.z, v1.w, hu[3], lu[3]);
        mysum += v0.x + v0.y + v0.z + v0.w + v1.x + v1.y + v1.z + v1.w;
        *(uint4*)&sH[0][sbase] = make_uint4(hu[0], hu[1], hu[2], hu[3]);
        *(uint4*)&sL[0][sbase] = make_uint4(lu[0], lu[1], lu[2], lu[3]);
    }
    __syncthreads();

    for (int ch = 0; ch < 32; ch++) {
        const int b = ch & 1;
        float4 n0, n1;
        if (ch < 31) {
            n0 = *(const float4*)(Xr + (ch + 1) * 16);
            n1 = *(const float4*)(Xr + (ch + 1) * 16 + 4);
        }

        const unsigned* cH = sH[b];
        const unsigned* cL = sL[b];
        unsigned Af[4][4];
#pragma unroll
        for (int m = 0; m < 4; m++) {
            const int ar = wr + m * 16 + qr;
            Af[m][0] = cH[ar * GPR + qc];
            Af[m][1] = cH[(ar + 8) * GPR + qc];
            Af[m][2] = cH[ar * GPR + qc + 4];
            Af[m][3] = cH[(ar + 8) * GPR + qc + 4];
        }
#pragma unroll
        for (int n = 0; n < 4; n++) {
            const int br = wc + n * 8 + qr;
            unsigned Bh[2] = {cH[br * GPR + qc], cH[br * GPR + qc + 4]};
            unsigned Bl[2] = {cL[br * GPR + qc], cL[br * GPR + qc + 4]};
#pragma unroll
            for (int m = 0; m < 4; m++) {
                mmah(acc[m][n], Af[m], Bh);
                mmah(acc[m][n], Af[m], Bl);
            }
        }

        if (ch < 31) {
            unsigned hu[4], lu[4];
            split2s2(n0.x, n0.y, hu[0], lu[0]);
            split2s2(n0.z, n0.w, hu[1], lu[1]);
            split2s2(n1.x, n1.y, hu[2], lu[2]);
            split2s2(n1.z, n1.w, hu[3], lu[3]);
            mysum += n0.x + n0.y + n0.z + n0.w + n1.x + n1.y + n1.z + n1.w;
            *(uint4*)&sH[b ^ 1][sbase] = make_uint4(hu[0], hu[1], hu[2], hu[3]);
            *(uint4*)&sL[b ^ 1][sbase] = make_uint4(lu[0], lu[1], lu[2], lu[3]);
        }
        __syncthreads();
    }

    sred[t] = mysum;
    __syncthreads();
    if (t < 128)
        g_spart[(bb * KSPLIT + kc) * CI + t] = sred[2 * t] + sred[2 * t + 1];

    float* P = g_Gpart + ((size_t)(bb * KSPLIT + kc)) * CI * CI;
#pragma unroll
    for (int m = 0; m < 4; m++) {
        const int r0 = wr + m * 16 + qr;
#pragma unroll
        for (int n = 0; n < 4; n++) {
            const int c0 = wc + n * 8 + qc * 2;
            *(float2*)(P + (size_t)r0 * CI + c0)       = make_float2(acc[m][n][0], acc[m][n][1]);
            *(float2*)(P + (size_t)(r0 + 8) * CI + c0) = make_float2(acc[m][n][2], acc[m][n][3]);
        }
    }
}

// =====================================================================
// Kernel 2: chain, tensorized. 64 CTAs, 256 threads.
// GEMM order (all operands natural row-major k-contiguous, G symmetric):
//   T1t[d][c] = sum_e  theta[d][e] * G[c][e]
//   L[c'][d]  = sum_c  phi[c'][c]  * T1t[d][c]
//   Mt[k][c]  = sum_d  gwT[k][d]   * f[c][d]
//   A''[r][j] = sum_c  Ww[r][c]    * Mt[j][c]   (+ scale, +I, fp16-split out)
// Packed buffers P0/P1 (hi+lo), fp32 scratch F32.
// =====================================================================
#define CH_PK   (128 * APR * 4)                 // one packed buffer: 34816 B
#define CH_OF32 (4 * CH_PK)                     // 139264
#define CH_SMEM (CH_OF32 + 128 * F32S * 4)      // 206848 B

// 3-product packed GEMM: O[m][n] = sum_k (Ah+Al)[m][k] * (Bh+Bl)[n][k]
__device__ __forceinline__ void mgh3(const unsigned* __restrict__ Ah,
                                     const unsigned* __restrict__ Al,
                                     const unsigned* __restrict__ Bh,
                                     const unsigned* __restrict__ Bl,
                                     float* __restrict__ O, int t)
{
    const int lane = t & 31, w = t >> 5;
    const int wr = (w >> 2) * 64, wc = (w & 3) * 32;
    const int qr = lane >> 2, qc = lane & 3;
    float acc[4][4][4];
#pragma unroll
    for (int m = 0; m < 4; m++)
#pragma unroll
        for (int n = 0; n < 4; n++)
#pragma unroll
            for (int r = 0; r < 4; r++) acc[m][n][r] = 0.f;

#pragma unroll
    for (int s = 0; s < 8; s++) {
        const int kp = s * 8;
        unsigned Afh[4][4], Afl[4][4];
#pragma unroll
        for (int m = 0; m < 4; m++) {
            const int ar = wr + m * 16 + qr;
            Afh[m][0] = Ah[ar * APR + kp + qc];
            Afh[m][1] = Ah[(ar + 8) * APR + kp + qc];
            Afh[m][2] = Ah[ar * APR + kp + qc + 4];
            Afh[m][3] = Ah[(ar + 8) * APR + kp + qc + 4];
            Afl[m][0] = Al[ar * APR + kp + qc];
            Afl[m][1] = Al[(ar + 8) * APR + kp + qc];
            Afl[m][2] = Al[ar * APR + kp + qc + 4];
            Afl[m][3] = Al[(ar + 8) * APR + kp + qc + 4];
        }
#pragma unroll
        for (int n = 0; n < 4; n++) {
            const int br = wc + n * 8 + qr;
            unsigned Bfh[2] = {Bh[br * APR + kp + qc], Bh[br * APR + kp + qc + 4]};
            unsigned Bfl[2] = {Bl[br * APR + kp + qc], Bl[br * APR + kp + qc + 4]};
#pragma unroll
            for (int m = 0; m < 4; m++) {
                mmah(acc[m][n], Afh[m], Bfh);
                mmah(acc[m][n], Afh[m], Bfl);
                mmah(acc[m][n], Afl[m], Bfh);
            }
        }
    }
#pragma unroll
    for (int m = 0; m < 4; m++) {
        const int r0 = wr + m * 16 + qr;
#pragma unroll
        for (int n = 0; n < 4; n++) {
            const int c0 = wc + n * 8 + qc * 2;
            *(float2*)&O[r0 * F32S + c0]       = make_float2(acc[m][n][0], acc[m][n][1]);
            *(float2*)&O[(r0 + 8) * F32S + c0] = make_float2(acc[m][n][2], acc[m][n][3]);
        }
    }
}

// final GEMM: epilogue scale + identity + fp16-split to global packed
__device__ __forceinline__ void mgh3_final(const unsigned* __restrict__ Ah,
                                           const unsigned* __restrict__ Al,
                                           const unsigned* __restrict__ Bh,
                                           const unsigned* __restrict__ Bl,
                                           unsigned* __restrict__ gAh,
                                           unsigned* __restrict__ gAl,
                                           const float* __restrict__ scale, int t)
{
    const int lane = t & 31, w = t >> 5;
    const int wr = (w >> 2) * 64, wc = (w & 3) * 32;
    const int qr = lane >> 2, qc = lane & 3;
    float acc[4][4][4];
#pragma unroll
    for (int m = 0; m < 4; m++)
#pragma unroll
        for (int n = 0; n < 4; n++)
#pragma unroll
            for (int r = 0; r < 4; r++) acc[m][n][r] = 0.f;

#pragma unroll
    for (int s = 0; s < 8; s++) {
        const int kp = s * 8;
        unsigned Afh[4][4], Afl[4][4];
#pragma unroll
        for (int m = 0; m < 4; m++) {
            const int ar = wr + m * 16 + qr;
            Afh[m][0] = Ah[ar * APR + kp + qc];
            Afh[m][1] = Ah[(ar + 8) * APR + kp + qc];
            Afh[m][2] = Ah[ar * APR + kp + qc + 4];
            Afh[m][3] = Ah[(ar + 8) * APR + kp + qc + 4];
            Afl[m][0] = Al[ar * APR + kp + qc];
            Afl[m][1] = Al[(ar + 8) * APR + kp + qc];
            Afl[m][2] = Al[ar * APR + kp + qc + 4];
            Afl[m][3] = Al[(ar + 8) * APR + kp + qc + 4];
        }
#pragma unroll
        for (int n = 0; n < 4; n++) {
            const int br = wc + n * 8 + qr;
            unsigned Bfh[2] = {Bh[br * APR + kp + qc], Bh[br * APR + kp + qc + 4]};
            unsigned Bfl[2] = {Bl[br * APR + kp + qc], Bl[br * APR + kp + qc + 4]};
#pragma unroll
            for (int m = 0; m < 4; m++) {
                mmah(acc[m][n], Afh[m], Bfh);
                mmah(acc[m][n], Afh[m], Bfl);
                mmah(acc[m][n], Afl[m], Bfh);
            }
        }
    }
#pragma unroll
    for (int m = 0; m < 4; m++) {
        const int r0 = wr + m * 16 + qr;
        const float s0 = scale[r0], s1 = scale[r0 + 8];
#pragma unroll
        for (int n = 0; n < 4; n++) {
            const int c0 = wc + n * 8 + qc * 2;
            float v0 = s0 * acc[m][n][0] + ((r0 == c0) ? 1.f : 0.f);
            float v1 = s0 * acc[m][n][1] + ((r0 == c0 + 1) ? 1.f : 0.f);
            float v2 = s1 * acc[m][n][2] + ((r0 + 8 == c0) ? 1.f : 0.f);
            float v3 = s1 * acc[m][n][3] + ((r0 + 8 == c0 + 1) ? 1.f : 0.f);
            unsigned hu, lu;
            split2(v0, v1, hu, lu);
            gAh[r0 * 64 + c0 / 2] = hu;
            gAl[r0 * 64 + c0 / 2] = lu;
            split2(v2, v3, hu, lu);
            gAh[(r0 + 8) * 64 + c0 / 2] = hu;
            gAl[(r0 + 8) * 64 + c0 / 2] = lu;
        }
    }
}

// stage gmem fp32 [128][128] natural -> packed hi/lo [row][e-pairs]
__device__ __forceinline__ void stage_pack_gmem(const float* __restrict__ src,
                                                unsigned* __restrict__ Ph,
                                                unsigned* __restrict__ Pl, int t)
{
    const int row = t >> 1, seg = (t & 1) * 64;
    const int base = row * APR + seg / 2;
    const float4* s4 = (const float4*)(src + row * CI + seg);
#pragma unroll
    for (int j = 0; j < 16; j++) {
        float4 v = s4[j];
        unsigned h0, l0, h1, l1;
        split2(v.x, v.y, h0, l0);
        split2(v.z, v.w, h1, l1);
        *(uint2*)&Ph[base + 2 * j] = make_uint2(h0, h1);
        *(uint2*)&Pl[base + 2 * j] = make_uint2(l0, l1);
    }
}

// pack smem fp32 [128][F32S] natural -> packed hi/lo
__device__ __forceinline__ void pack_from_smem(const float* __restrict__ F,
                                               unsigned* __restrict__ Ph,
                                               unsigned* __restrict__ Pl, int t)
{
    const int row = t >> 1, seg = (t & 1) * 64;
    const int base = row * APR + seg / 2;
    const float* fr = F + row * F32S + seg;
#pragma unroll
    for (int j = 0; j < 32; j++) {
        float2 v = *(const float2*)(fr + 2 * j);
        unsigned h, l;
        split2(v.x, v.y, h, l);
        Ph[base + j] = h;
        Pl[base + j] = l;
    }
}

// dot of packed row (h+l reconstruct) with fp32 vector
__device__ __forceinline__ float dot_packed(const unsigned* __restrict__ Ph,
                                            const unsigned* __restrict__ Pl,
                                            int row, const float* __restrict__ s)
{
    float acc = 0.f;
#pragma unroll 8
    for (int p = 0; p < 64; p++) {
        float2 hf = __half22float2(*(const __half2*)&Ph[row * APR + p]);
        float2 lf = __half22float2(*(const __half2*)&Pl[row * APR + p]);
        acc += (hf.x + lf.x) * s[2 * p] + (hf.y + lf.y) * s[2 * p + 1];
    }
    return acc;
}

__global__ void __launch_bounds__(256)
chain_kernel(const float* __restrict__ theta_w, const float* __restrict__ theta_b,
             const float* __restrict__ phi_w,   const float* __restrict__ phi_b,
             const float* __restrict__ g_w,     const float* __restrict__ g_b,
             const float* __restrict__ W_w,     const float* __restrict__ W_b,
             const float* __restrict__ bn_gamma, const float* __restrict__ bn_beta,
             const float* __restrict__ bn_mean,  const float* __restrict__ bn_var)
{
    extern __shared__ char csm[];
    unsigned* P0h = (unsigned*)(csm);
    unsigned* P0l = (unsigned*)(csm + CH_PK);
    unsigned* P1h = (unsigned*)(csm + 2 * CH_PK);
    unsigned* P1l = (unsigned*)(csm + 3 * CH_PK);
    float*    F32 = (float*)(csm + CH_OF32);      // [128][F32S]

    __shared__ float sv_s[CI], sv_u[CI], sv_q[CI], sv_tb[CI],
                     sv_gb[CI], sv_c[CI], sv_scale[CI];

    const int t  = threadIdx.x;
    const int bb = blockIdx.x;

    // --- 1) assemble S into F32; vectors; stage theta packed -> P1 ---
    const float* Gp = g_Gpart + (size_t)bb * KSPLIT * CI * CI;
    for (int idx = t; idx < CI * CI; idx += 256) {
        float v = 0.f;
#pragma unroll
        for (int ks = 0; ks < KSPLIT; ks++) v += Gp[ks * CI * CI + idx];
        F32[(idx >> 7) * F32S + (idx & 127)] = v;
    }
    if (t < CI) {
        float v = 0.f;
#pragma unroll
        for (int ks = 0; ks < KSPLIT; ks++) v += g_spart[(bb * KSPLIT + ks) * CI + t];
        sv_s[t]  = v;
        sv_tb[t] = theta_b[t];
        sv_gb[t] = g_b[t];
        sv_scale[t] = bn_gamma[t] * rsqrtf(bn_var[t] + 1e-5f);
    }
    stage_pack_gmem(theta_w, P1h, P1l, t);
    __syncthreads();

    // --- 2) symmetrize S in place (each thread owns disjoint (r,c)/(c,r)) ---
    for (int i = t; i < 8256; i += 256) {
        int r = (int)((sqrtf(8.0f * (float)i + 1.0f) - 1.0f) * 0.5f);
        if ((r + 1) * (r + 2) / 2 <= i) r++;
        if (r * (r + 1) / 2 > i) r--;
        int c = i - r * (r + 1) / 2;
        float a = F32[r * F32S + c], b = F32[c * F32S + r];
        float g = 0.5f * (a + b);
        F32[r * F32S + c] = g;
        F32[c * F32S + r] = g;
    }
    if (t < CI)
        sv_q[t] = dot_packed(P1h, P1l, t, sv_s) + 4096.0f * sv_tb[t];
    __syncthreads();

    // --- 3) pack G -> P0 ---
    pack_from_smem(F32, P0h, P0l, t);
    __syncthreads();

    // --- 4) GEMM1: T1t[d][c] = theta x G -> F32 ---
    mgh3(P1h, P1l, P0h, P0l, F32, t);
    __syncthreads();

    // --- 5) pack T1t -> P0; stage phi -> P1 ---
    pack_from_smem(F32, P0h, P0l, t);
    stage_pack_gmem(phi_w, P1h, P1l, t);
    __syncthreads();
    if (t < CI)
        sv_u[t] = dot_packed(P1h, P1l, t, sv_s);
    __syncthreads();

    // --- 6) GEMM2: L[c'][d] = phi x T1t -> F32 ---
    mgh3(P1h, P1l, P0h, P0l, F32, t);
    __syncthreads();

    // --- 7) softmax rows (fp32) -> f packed into P1; sv_c ---
    if (t < CI) {
        const float w1 = sv_u[t];
        const float w2 = phi_b[t];
        float* rowp = F32 + t * F32S;
        float mx = -1e30f;
#pragma unroll 8
        for (int d = 0; d < 128; d++) {
            float v = rowp[d] + w1 * sv_tb[d] + w2 * sv_q[d];
            rowp[d] = v;
            mx = fmaxf(mx, v);
        }
        float ssum = 0.f;
#pragma unroll 8
        for (int d = 0; d < 128; d++) {
            float ev = expf(rowp[d] - mx);
            rowp[d] = ev;
            ssum += ev;
        }
        const float inv = 1.0f / ssum;
        float cacc = 0.f;
#pragma unroll
        for (int p = 0; p < 64; p++) {
            float f0 = rowp[2 * p] * inv;
            float f1 = rowp[2 * p + 1] * inv;
            cacc += f0 * sv_gb[2 * p] + f1 * sv_gb[2 * p + 1];
            unsigned h, l;
            split2(f0, f1, h, l);
            P1h[t * APR + p] = h;
            P1l[t * APR + p] = l;
        }
        sv_c[t] = cacc;
    }
    __syncthreads();

    // --- 8) gw natural -> F32, then transpose-pack gwT -> P0 ---
    for (int idx = t; idx < CI * CI; idx += 256)
        F32[(idx >> 7) * F32S + (idx & 127)] = g_w[idx];
    __syncthreads();
    {
        const int k = t >> 1, d0 = (t & 1) * 64;
        const int base = k * APR + d0 / 2;
#pragma unroll
        for (int p = 0; p < 32; p++) {
            const int d = d0 + 2 * p;
            unsigned h, l;
            split2(F32[d * F32S + k], F32[(d + 1) * F32S + k], h, l);
            P0h[base + p] = h;
            P0l[base + p] = l;
        }
    }
    __syncthreads();

    // --- 9) GEMM3: Mt[k][c] = gwT x f -> F32 ---
    mgh3(P0h, P0l, P1h, P1l, F32, t);
    __syncthreads();

    // --- 10) pack Mt -> P0; stage Ww -> P1; bias ---
    pack_from_smem(F32, P0h, P0l, t);
    stage_pack_gmem(W_w, P1h, P1l, t);
    __syncthreads();
    if (t < CI) {
        float b0 = dot_packed(P1h, P1l, t, sv_c);
        float sc = sv_scale[t];
        g_bvec[bb * CI + t] = sc * (b0 + W_b[t]) + bn_beta[t] - bn_mean[t] * sc;
    }

    // --- 11) GEMM4: A'' = Ww x Mt -> global packed (scale + I) ---
    mgh3_final(P1h, P1l, P0h, P0l,
               g_Ah2 + (size_t)bb * CI * 64, g_Al2 + (size_t)bb * CI * 64,
               sv_scale, t);
}

// =====================================================================
// Kernel 3: Z = A'' X + b' via fp16 3-product m16n8k16, single wave.
// =====================================================================
#define AP_SMEM ((2 * 128 * APR + 4 * 16 * XPR) * 4)   // 137216 B

__global__ void __launch_bounds__(512)
apply_kernel(const float* __restrict__ X, float* __restrict__ Z)
{
    extern __shared__ unsigned apsm[];
    unsigned* sAh = apsm;                       // [128][APR]
    unsigned* sAl = sAh + 128 * APR;
    unsigned* sXh[2] = {sAl + 128 * APR, sAl + 128 * APR + 16 * XPR};
    unsigned* sXl[2] = {sAl + 128 * APR + 2 * 16 * XPR,
                        sAl + 128 * APR + 3 * 16 * XPR};

    const int t = threadIdx.x;
    const int lane = t & 31, w = t >> 5;
    const int wr = (w >> 2) * 32;
    const int wc = (w & 3) * 64;
    const int qr = lane >> 2, qc = lane & 3;
    const int bb = blockIdx.y;
    const int half0 = blockIdx.x * 2048;

    {
        const int row = t >> 2, seg = (t & 3) * 16;
        const uint4* Ah = (const uint4*)(g_Ah2 + ((size_t)bb * CI + row) * 64 + seg);
        const uint4* Al = (const uint4*)(g_Al2 + ((size_t)bb * CI + row) * 64 + seg);
#pragma unroll
        for (int j = 0; j < 4; j++) {
            *(uint4*)&sAh[row * APR + seg + 4 * j] = Ah[j];
            *(uint4*)&sAl[row * APR + seg + 4 * j] = Al[j];
        }
    }

    float bias[2][2];
#pragma unroll
    for (int m = 0; m < 2; m++) {
        bias[m][0] = g_bvec[bb * CI + wr + m * 16 + qr];
        bias[m][1] = g_bvec[bb * CI + wr + m * 16 + qr + 8];
    }

    const float* Xb = X + (size_t)bb * CI * NPIX;
    float* Zb = Z + (size_t)bb * CI * NPIX;

    const int lp = w;
    const int lpx = lane * 8;

    float acc[2][8][4];
#pragma unroll
    for (int m = 0; m < 2; m++)
#pragma unroll
        for (int n = 0; n < 8; n++)
#pragma unroll
            for (int r = 0; r < 4; r++) acc[m][n][r] = 0.f;

    {
        const float* se = Xb + (size_t)(2 * lp) * NPIX + half0 + lpx;
        const float* so = Xb + (size_t)(2 * lp + 1) * NPIX + half0 + lpx;
        float4 e0 = *(const float4*)(se), e1 = *(const float4*)(se + 4);
        float4 o0 = *(const float4*)(so), o1 = *(const float4*)(so + 4);
        float ev[8] = {e0.x, e0.y, e0.z, e0.w, e1.x, e1.y, e1.z, e1.w};
        float ov[8] = {o0.x, o0.y, o0.z, o0.w, o1.x, o1.y, o1.z, o1.w};
        unsigned hu[8], lu[8];
#pragma unroll
        for (int i = 0; i < 8; i++) split2(ev[i], ov[i], hu[i], lu[i]);
        *(uint4*)&sXh[0][lp * XPR + lpx]     = make_uint4(hu[0], hu[1], hu[2], hu[3]);
        *(uint4*)&sXh[0][lp * XPR + lpx + 4] = make_uint4(hu[4], hu[5], hu[6], hu[7]);
        *(uint4*)&sXl[0][lp * XPR + lpx]     = make_uint4(lu[0], lu[1], lu[2], lu[3]);
        *(uint4*)&sXl[0][lp * XPR + lpx + 4] = make_uint4(lu[4], lu[5], lu[6], lu[7]);
    }
    __syncthreads();

    for (int c = 0; c < 32; c++) {
        const int b = c & 1;
        const int g = c & 3;

        float4 ne0, ne1, no0, no1;
        if (c < 31) {
            const int ng = (c + 1) & 3, ns = (c + 1) >> 2;
            const float* se = Xb + (size_t)(ng * 32 + 2 * lp) * NPIX + half0 + ns * 256 + lpx;
            const float* so = se + NPIX;
            ne0 = *(const float4*)(se); ne1 = *(const float4*)(se + 4);
            no0 = *(const float4*)(so); no1 = *(const float4*)(so + 4);
        }

#pragma unroll
        for (int ks = 0; ks < 2; ks++) {
            const int kp0 = ks * 8;
            const int ga = g * 16 + kp0;
            unsigned Ahf[2][4], Alf[2][4];
#pragma unroll
            for (int m = 0; m < 2; m++) {
                const int ar = wr + m * 16 + qr;
                Ahf[m][0] = sAh[ar * APR + ga + qc];
                Ahf[m][1] = sAh[(ar + 8) * APR + ga + qc];
                Ahf[m][2] = sAh[ar * APR + ga + qc + 4];
                Ahf[m][3] = sAh[(ar + 8) * APR + ga + qc + 4];
                Alf[m][0] = sAl[ar * APR + ga + qc];
                Alf[m][1] = sAl[(ar + 8) * APR + ga + qc];
                Alf[m][2] = sAl[ar * APR + ga + qc + 4];
                Alf[m][3] = sAl[(ar + 8) * APR + ga + qc + 4];
            }
#pragma unroll
            for (int n = 0; n < 8; n++) {
                const int bpx = wc + n * 8 + qr;
                unsigned Bh[2] = {sXh[b][(kp0 + qc) * XPR + bpx],
                                  sXh[b][(kp0 + qc + 4) * XPR + bpx]};
                unsigned Bl[2] = {sXl[b][(kp0 + qc) * XPR + bpx],
                                  sXl[b][(kp0 + qc + 4) * XPR + bpx]};
#pragma unroll
                for (int m = 0; m < 2; m++) {
                    mmah(acc[m][n], Ahf[m], Bh);
                    mmah(acc[m][n], Ahf[m], Bl);
                    mmah(acc[m][n], Alf[m], Bh);
                }
            }
        }

        if (c < 31) {
            float ev[8] = {ne0.x, ne0.y, ne0.z, ne0.w, ne1.x, ne1.y, ne1.z, ne1.w};
            float ov[8] = {no0.x, no0.y, no0.z, no0.w, no1.x, no1.y, no1.z, no1.w};
            unsigned hu[8], lu[8];
#pragma unroll
            for (int i = 0; i < 8; i++) split2(ev[i], ov[i], hu[i], lu[i]);
            unsigned* dh = &sXh[b ^ 1][lp * XPR + lpx];
            unsigned* dl = &sXl[b ^ 1][lp * XPR + lpx];
            *(uint4*)(dh)     = make_uint4(hu[0], hu[1], hu[2], hu[3]);
            *(uint4*)(dh + 4) = make_uint4(hu[4], hu[5], hu[6], hu[7]);
            *(uint4*)(dl)     = make_uint4(lu[0], lu[1], lu[2], lu[3]);
            *(uint4*)(dl + 4) = make_uint4(lu[4], lu[5], lu[6], lu[7]);
        }
        __syncthreads();

        if (g == 3) {
            const int px0 = half0 + (c >> 2) * 256;
#pragma unroll
            for (int m = 0; m < 2; m++) {
                const int r0 = wr + m * 16 + qr;
#pragma unroll
                for (int n = 0; n < 8; n++) {
                    const int c0 = px0 + wc + n * 8 + qc * 2;
                    *(float2*)(Zb + (size_t)r0 * NPIX + c0) =
                        make_float2(acc[m][n][0] + bias[m][0], acc[m][n][1] + bias[m][0]);
                    *(float2*)(Zb + (size_t)(r0 + 8) * NPIX + c0) =
                        make_float2(acc[m][n][2] + bias[m][1], acc[m][n][3] + bias[m][1]);
                }
            }
#pragma unroll
            for (int m = 0; m < 2; m++)
#pragma unroll
                for (int n = 0; n < 8; n++)
#pragma unroll
                    for (int r = 0; r < 4; r++) acc[m][n][r] = 0.f;
        }
    }
}

// =====================================================================
extern "C" void kernel_launch(void* const* d_in, const int* in_sizes, int n_in,
                              void* d_out, int out_size)
{
    (void)in_sizes; (void)n_in; (void)out_size;
    const float* x        = (const float*)d_in[0];
    const float* theta_w  = (const float*)d_in[1];
    const float* theta_b  = (const float*)d_in[2];
    const float* phi_w    = (const float*)d_in[3];
    const float* phi_b    = (const float*)d_in[4];
    const float* g_w      = (const float*)d_in[5];
    const float* g_b      = (const float*)d_in[6];
    const float* W_w      = (const float*)d_in[7];
    const float* W_b      = (const float*)d_in[8];
    const float* bn_gamma = (const float*)d_in[9];
    const float* bn_beta  = (const float*)d_in[10];
    const float* bn_mean  = (const float*)d_in[11];
    const float* bn_var   = (const float*)d_in[12];
    float* out = (float*)d_out;

    cudaFuncSetAttribute(chain_kernel,
                         cudaFuncAttributeMaxDynamicSharedMemorySize, CH_SMEM);
    cudaFuncSetAttribute(apply_kernel,
                         cudaFuncAttributeMaxDynamicSharedMemorySize, AP_SMEM);

    gram_kernel<<<dim3(KSPLIT, NB), 256>>>(x);
    chain_kernel<<<NB, 256, CH_SMEM>>>(theta_w, theta_b, phi_w, phi_b,
                                       g_w, g_b, W_w, W_b,
                                       bn_gamma, bn_beta, bn_mean, bn_var);
    apply_kernel<<<dim3(2, NB), 512, AP_SMEM>>>(x, out);
}

// round 11
// speedup vs baseline: 2.1086x; 1.0317x over previous
#include <cuda_runtime.h>
#include <cuda_fp16.h>
#include <cstdint>
#include <math.h>

// Problem constants:
//  x: [16, 512, 64, 64] fp32 == [64 batches][128 ch][4096 px] contiguous
#define NB     64
#define CI     128
#define NPIX   4096
#define KSPLIT 8                 // gram K-split CTAs per batch (K=512 each)
#define GPR    12                // gram pair stride (8 pairs + 4)  [48B, ldsm-conflict-free]
#define APR    68                // packed pair stride (64 pairs + 4) [272B, ldsm-conflict-free]
#define XST2   132               // apply X row stride in uints ([ch][px]: 128 + 4) [528B, cf]
#define F32S   132               // chain fp32 scratch stride

// ---------------- fp16 helpers ----------------
__device__ __forceinline__ void split2(float a, float b, unsigned& hu, unsigned& lu) {
    __half2 h2 = __float22half2_rn(make_float2(a, b));
    float2 hf = __half22float2(h2);
    __half2 l2 = __float22half2_rn(make_float2(a - hf.x, b - hf.y));
    hu = *(unsigned*)&h2;
    lu = *(unsigned*)&l2;
}
__device__ __forceinline__ void split2s2(float a, float b, unsigned& hu, unsigned& lu) {
    __half2 h2 = __float22half2_rn(make_float2(a, b));
    float2 hf = __half22float2(h2);
    __half2 l2 = __float22half2_rn(make_float2((a - hf.x) * 2.0f, (b - hf.y) * 2.0f));
    hu = *(unsigned*)&h2;
    lu = *(unsigned*)&l2;
}

// D += A(16x16,row,f16) * B(16x8,col,f16)  fp32-accum
__device__ __forceinline__ void mmah(float* d, const unsigned* a, const unsigned* b) {
    asm volatile(
        "mma.sync.aligned.m16n8k16.row.col.f32.f16.f16.f32 "
        "{%0,%1,%2,%3}, {%4,%5,%6,%7}, {%8,%9}, {%0,%1,%2,%3};"
        : "+f"(d[0]), "+f"(d[1]), "+f"(d[2]), "+f"(d[3])
        : "r"(a[0]), "r"(a[1]), "r"(a[2]), "r"(a[3]), "r"(b[0]), "r"(b[1]));
}

__device__ __forceinline__ uint32_t s2u(const void* p) {
    return (uint32_t)__cvta_generic_to_shared(p);
}
#define LDSM_X4(r, addr) \
    asm volatile("ldmatrix.sync.aligned.m8n8.x4.shared.b16 {%0,%1,%2,%3}, [%4];" \
        : "=r"((r)[0]), "=r"((r)[1]), "=r"((r)[2]), "=r"((r)[3]) : "r"(addr))
#define LDSM_X4T(r, addr) \
    asm volatile("ldmatrix.sync.aligned.m8n8.x4.trans.shared.b16 {%0,%1,%2,%3}, [%4];" \
        : "=r"((r)[0]), "=r"((r)[1]), "=r"((r)[2]), "=r"((r)[3]) : "r"(addr))

// ---------------- scratch ----------------
__device__ float    g_Gpart[NB * KSPLIT * CI * CI]; // partial E (G = (E+E^T)/2)
__device__ float    g_spart[NB * KSPLIT * CI];      // partial row sums
__device__ unsigned g_Ah2[NB * CI * 64];            // A'' fp16-hi, half2 pairs
__device__ unsigned g_Al2[NB * CI * 64];            // A'' fp16-lo, half2 pairs
__device__ float    g_bvec[NB * CI];                // folded bias b'

// =====================================================================
// Kernel 1: partial E = H H^T + H (2L)^T via fp16 m16n8k16 + ldmatrix.
// grid (KSPLIT, NB), 256 threads, 2 CTAs/SM. 32 chunks of 16 px.
// =====================================================================
__global__ void __launch_bounds__(256, 2)
gram_kernel(const float* __restrict__ X)
{
    __shared__ unsigned sH[2][128 * GPR];
    __shared__ unsigned sL[2][128 * GPR];
    __shared__ float sred[256];

    const int t = threadIdx.x;
    const int lane = t & 31, w = t >> 5;
    const int wr = (w >> 2) * 64, wc = (w & 3) * 32;
    const int qr = lane >> 2, qc = lane & 3;
    const int kc = blockIdx.x, bb = blockIdx.y;

    const float* Xb = X + (size_t)bb * CI * NPIX + (size_t)kc * 512;
    const int lrow = t >> 1, lp4 = (t & 1) * 4;
    const int sbase = lrow * GPR + lp4;
    const float* Xr = Xb + (size_t)lrow * NPIX + lp4 * 2;

    const uint32_t aH[2] = {s2u(sH[0]), s2u(sH[1])};
    const uint32_t aL[2] = {s2u(sL[0]), s2u(sL[1])};

    // per-lane ldmatrix address offsets (bytes)
    uint32_t aoffA[4], boffB[2];
#pragma unroll
    for (int m = 0; m < 4; m++)
        aoffA[m] = (uint32_t)((wr + m * 16 + (lane & 15)) * GPR) * 4u
                 + (uint32_t)((lane >> 4) & 1) * 16u;
#pragma unroll
    for (int j = 0; j < 2; j++)
        boffB[j] = (uint32_t)((wc + j * 16 + (lane & 7) + ((lane >> 4) & 1) * 8) * GPR) * 4u
                 + (uint32_t)((lane >> 3) & 1) * 16u;

    float acc[4][4][4];
#pragma unroll
    for (int m = 0; m < 4; m++)
#pragma unroll
        for (int n = 0; n < 4; n++)
#pragma unroll
            for (int r = 0; r < 4; r++) acc[m][n][r] = 0.f;
    float mysum = 0.f;

    {
        float4 v0 = *(const float4*)(Xr);
        float4 v1 = *(const float4*)(Xr + 4);
        unsigned hu[4], lu[4];
        split2s2(v0.x, v0.y, hu[0], lu[0]);
        split2s2(v0.z, v0.w, hu[1], lu[1]);
        split2s2(v1.x, v1.y, hu[2], lu[2]);
        split2s2(v1.z, v1.w, hu[3], lu[3]);
        mysum += v0.x + v0.y + v0.z + v0.w + v1.x + v1.y + v1.z + v1.w;
        *(uint4*)&sH[0][sbase] = make_uint4(hu[0], hu[1], hu[2], hu[3]);
        *(uint4*)&sL[0][sbase] = make_uint4(lu[0], lu[1], lu[2], lu[3]);
    }
    __syncthreads();

    for (int ch = 0; ch < 32; ch++) {
        const int b = ch & 1;
        float4 n0, n1;
        if (ch < 31) {
            n0 = *(const float4*)(Xr + (ch + 1) * 16);
            n1 = *(const float4*)(Xr + (ch + 1) * 16 + 4);
        }

        unsigned Af[4][4];
#pragma unroll
        for (int m = 0; m < 4; m++) LDSM_X4(Af[m], aH[b] + aoffA[m]);
#pragma unroll
        for (int j = 0; j < 2; j++) {
            unsigned BH[4], BL[4];
            LDSM_X4(BH, aH[b] + boffB[j]);
            LDSM_X4(BL, aL[b] + boffB[j]);
            unsigned B0h[2] = {BH[0], BH[1]}, B1h[2] = {BH[2], BH[3]};
            unsigned B0l[2] = {BL[0], BL[1]}, B1l[2] = {BL[2], BL[3]};
#pragma unroll
            for (int m = 0; m < 4; m++) {
                mmah(acc[m][2 * j],     Af[m], B0h);
                mmah(acc[m][2 * j],     Af[m], B0l);
                mmah(acc[m][2 * j + 1], Af[m], B1h);
                mmah(acc[m][2 * j + 1], Af[m], B1l);
            }
        }

        if (ch < 31) {
            unsigned hu[4], lu[4];
            split2s2(n0.x, n0.y, hu[0], lu[0]);
            split2s2(n0.z, n0.w, hu[1], lu[1]);
            split2s2(n1.x, n1.y, hu[2], lu[2]);
            split2s2(n1.z, n1.w, hu[3], lu[3]);
            mysum += n0.x + n0.y + n0.z + n0.w + n1.x + n1.y + n1.z + n1.w;
            *(uint4*)&sH[b ^ 1][sbase] = make_uint4(hu[0], hu[1], hu[2], hu[3]);
            *(uint4*)&sL[b ^ 1][sbase] = make_uint4(lu[0], lu[1], lu[2], lu[3]);
        }
        __syncthreads();
    }

    sred[t] = mysum;
    __syncthreads();
    if (t < 128)
        g_spart[(bb * KSPLIT + kc) * CI + t] = sred[2 * t] + sred[2 * t + 1];

    float* P = g_Gpart + ((size_t)(bb * KSPLIT + kc)) * CI * CI;
#pragma unroll
    for (int m = 0; m < 4; m++) {
        const int r0 = wr + m * 16 + qr;
#pragma unroll
        for (int n = 0; n < 4; n++) {
            const int c0 = wc + n * 8 + qc * 2;
            *(float2*)(P + (size_t)r0 * CI + c0)       = make_float2(acc[m][n][0], acc[m][n][1]);
            *(float2*)(P + (size_t)(r0 + 8) * CI + c0) = make_float2(acc[m][n][2], acc[m][n][3]);
        }
    }
}

// =====================================================================
// Kernel 2: chain, tensorized (round-10 proven, unchanged).
// =====================================================================
#define CH_PK   (128 * APR * 4)
#define CH_OF32 (4 * CH_PK)
#define CH_SMEM (CH_OF32 + 128 * F32S * 4)

__device__ __forceinline__ void mgh3(const unsigned* __restrict__ Ah,
                                     const unsigned* __restrict__ Al,
                                     const unsigned* __restrict__ Bh,
                                     const unsigned* __restrict__ Bl,
                                     float* __restrict__ O, int t)
{
    const int lane = t & 31, w = t >> 5;
    const int wr = (w >> 2) * 64, wc = (w & 3) * 32;
    const int qr = lane >> 2, qc = lane & 3;
    float acc[4][4][4];
#pragma unroll
    for (int m = 0; m < 4; m++)
#pragma unroll
        for (int n = 0; n < 4; n++)
#pragma unroll
            for (int r = 0; r < 4; r++) acc[m][n][r] = 0.f;

#pragma unroll
    for (int s = 0; s < 8; s++) {
        const int kp = s * 8;
        unsigned Afh[4][4], Afl[4][4];
#pragma unroll
        for (int m = 0; m < 4; m++) {
            const int ar = wr + m * 16 + qr;
            Afh[m][0] = Ah[ar * APR + kp + qc];
            Afh[m][1] = Ah[(ar + 8) * APR + kp + qc];
            Afh[m][2] = Ah[ar * APR + kp + qc + 4];
            Afh[m][3] = Ah[(ar + 8) * APR + kp + qc + 4];
            Afl[m][0] = Al[ar * APR + kp + qc];
            Afl[m][1] = Al[(ar + 8) * APR + kp + qc];
            Afl[m][2] = Al[ar * APR + kp + qc + 4];
            Afl[m][3] = Al[(ar + 8) * APR + kp + qc + 4];
        }
#pragma unroll
        for (int n = 0; n < 4; n++) {
            const int br = wc + n * 8 + qr;
            unsigned Bfh[2] = {Bh[br * APR + kp + qc], Bh[br * APR + kp + qc + 4]};
            unsigned Bfl[2] = {Bl[br * APR + kp + qc], Bl[br * APR + kp + qc + 4]};
#pragma unroll
            for (int m = 0; m < 4; m++) {
                mmah(acc[m][n], Afh[m], Bfh);
                mmah(acc[m][n], Afh[m], Bfl);
                mmah(acc[m][n], Afl[m], Bfh);
            }
        }
    }
#pragma unroll
    for (int m = 0; m < 4; m++) {
        const int r0 = wr + m * 16 + qr;
#pragma unroll
        for (int n = 0; n < 4; n++) {
            const int c0 = wc + n * 8 + qc * 2;
            *(float2*)&O[r0 * F32S + c0]       = make_float2(acc[m][n][0], acc[m][n][1]);
            *(float2*)&O[(r0 + 8) * F32S + c0] = make_float2(acc[m][n][2], acc[m][n][3]);
        }
    }
}

__device__ __forceinline__ void mgh3_final(const unsigned* __restrict__ Ah,
                                           const unsigned* __restrict__ Al,
                                           const unsigned* __restrict__ Bh,
                                           const unsigned* __restrict__ Bl,
                                           unsigned* __restrict__ gAh,
                                           unsigned* __restrict__ gAl,
                                           const float* __restrict__ scale, int t)
{
    const int lane = t & 31, w = t >> 5;
    const int wr = (w >> 2) * 64, wc = (w & 3) * 32;
    const int qr = lane >> 2, qc = lane & 3;
    float acc[4][4][4];
#pragma unroll
    for (int m = 0; m < 4; m++)
#pragma unroll
        for (int n = 0; n < 4; n++)
#pragma unroll
            for (int r = 0; r < 4; r++) acc[m][n][r] = 0.f;

#pragma unroll
    for (int s = 0; s < 8; s++) {
        const int kp = s * 8;
        unsigned Afh[4][4], Afl[4][4];
#pragma unroll
        for (int m = 0; m < 4; m++) {
            const int ar = wr + m * 16 + qr;
            Afh[m][0] = Ah[ar * APR + kp + qc];
            Afh[m][1] = Ah[(ar + 8) * APR + kp + qc];
            Afh[m][2] = Ah[ar * APR + kp + qc + 4];
            Afh[m][3] = Ah[(ar + 8) * APR + kp + qc + 4];
            Afl[m][0] = Al[ar * APR + kp + qc];
            Afl[m][1] = Al[(ar + 8) * APR + kp + qc];
            Afl[m][2] = Al[ar * APR + kp + qc + 4];
            Afl[m][3] = Al[(ar + 8) * APR + kp + qc + 4];
        }
#pragma unroll
        for (int n = 0; n < 4; n++) {
            const int br = wc + n * 8 + qr;
            unsigned Bfh[2] = {Bh[br * APR + kp + qc], Bh[br * APR + kp + qc + 4]};
            unsigned Bfl[2] = {Bl[br * APR + kp + qc], Bl[br * APR + kp + qc + 4]};
#pragma unroll
            for (int m = 0; m < 4; m++) {
                mmah(acc[m][n], Afh[m], Bfh);
                mmah(acc[m][n], Afh[m], Bfl);
                mmah(acc[m][n], Afl[m], Bfh);
            }
        }
    }
#pragma unroll
    for (int m = 0; m < 4; m++) {
        const int r0 = wr + m * 16 + qr;
        const float s0 = scale[r0], s1 = scale[r0 + 8];
#pragma unroll
        for (int n = 0; n < 4; n++) {
            const int c0 = wc + n * 8 + qc * 2;
            float v0 = s0 * acc[m][n][0] + ((r0 == c0) ? 1.f : 0.f);
            float v1 = s0 * acc[m][n][1] + ((r0 == c0 + 1) ? 1.f : 0.f);
            float v2 = s1 * acc[m][n][2] + ((r0 + 8 == c0) ? 1.f : 0.f);
            float v3 = s1 * acc[m][n][3] + ((r0 + 8 == c0 + 1) ? 1.f : 0.f);
            unsigned hu, lu;
            split2(v0, v1, hu, lu);
            gAh[r0 * 64 + c0 / 2] = hu;
            gAl[r0 * 64 + c0 / 2] = lu;
            split2(v2, v3, hu, lu);
            gAh[(r0 + 8) * 64 + c0 / 2] = hu;
            gAl[(r0 + 8) * 64 + c0 / 2] = lu;
        }
    }
}

__device__ __forceinline__ void stage_pack_gmem(const float* __restrict__ src,
                                                unsigned* __restrict__ Ph,
                                                unsigned* __restrict__ Pl, int t)
{
    const int row = t >> 1, seg = (t & 1) * 64;
    const int base = row * APR + seg / 2;
    const float4* s4 = (const float4*)(src + row * CI + seg);
#pragma unroll
    for (int j = 0; j < 16; j++) {
        float4 v = s4[j];
        unsigned h0, l0, h1, l1;
        split2(v.x, v.y, h0, l0);
        split2(v.z, v.w, h1, l1);
        *(uint2*)&Ph[base + 2 * j] = make_uint2(h0, h1);
        *(uint2*)&Pl[base + 2 * j] = make_uint2(l0, l1);
    }
}

__device__ __forceinline__ void pack_from_smem(const float* __restrict__ F,
                                               unsigned* __restrict__ Ph,
                                               unsigned* __restrict__ Pl, int t)
{
    const int row = t >> 1, seg = (t & 1) * 64;
    const int base = row * APR + seg / 2;
    const float* fr = F + row * F32S + seg;
#pragma unroll
    for (int j = 0; j < 32; j++) {
        float2 v = *(const float2*)(fr + 2 * j);
        unsigned h, l;
        split2(v.x, v.y, h, l);
        Ph[base + j] = h;
        Pl[base + j] = l;
    }
}

__device__ __forceinline__ float dot_packed(const unsigned* __restrict__ Ph,
                                            const unsigned* __restrict__ Pl,
                                            int row, const float* __restrict__ s)
{
    float acc = 0.f;
#pragma unroll 8
    for (int p = 0; p < 64; p++) {
        float2 hf = __half22float2(*(const __half2*)&Ph[row * APR + p]);
        float2 lf = __half22float2(*(const __half2*)&Pl[row * APR + p]);
        acc += (hf.x + lf.x) * s[2 * p] + (hf.y + lf.y) * s[2 * p + 1];
    }
    return acc;
}

__global__ void __launch_bounds__(256)
chain_kernel(const float* __restrict__ theta_w, const float* __restrict__ theta_b,
             const float* __restrict__ phi_w,   const float* __restrict__ phi_b,
             const float* __restrict__ g_w,     const float* __restrict__ g_b,
             const float* __restrict__ W_w,     const float* __restrict__ W_b,
             const float* __restrict__ bn_gamma, const float* __restrict__ bn_beta,
             const float* __restrict__ bn_mean,  const float* __restrict__ bn_var)
{
    extern __shared__ char csm[];
    unsigned* P0h = (unsigned*)(csm);
    unsigned* P0l = (unsigned*)(csm + CH_PK);
    unsigned* P1h = (unsigned*)(csm + 2 * CH_PK);
    unsigned* P1l = (unsigned*)(csm + 3 * CH_PK);
    float*    F32 = (float*)(csm + CH_OF32);

    __shared__ float sv_s[CI], sv_u[CI], sv_q[CI], sv_tb[CI],
                     sv_gb[CI], sv_c[CI], sv_scale[CI];

    const int t  = threadIdx.x;
    const int bb = blockIdx.x;

    const float* Gp = g_Gpart + (size_t)bb * KSPLIT * CI * CI;
    for (int idx = t; idx < CI * CI; idx += 256) {
        float v = 0.f;
#pragma unroll
        for (int ks = 0; ks < KSPLIT; ks++) v += Gp[ks * CI * CI + idx];
        F32[(idx >> 7) * F32S + (idx & 127)] = v;
    }
    if (t < CI) {
        float v = 0.f;
#pragma unroll
        for (int ks = 0; ks < KSPLIT; ks++) v += g_spart[(bb * KSPLIT + ks) * CI + t];
        sv_s[t]  = v;
        sv_tb[t] = theta_b[t];
        sv_gb[t] = g_b[t];
        sv_scale[t] = bn_gamma[t] * rsqrtf(bn_var[t] + 1e-5f);
    }
    stage_pack_gmem(theta_w, P1h, P1l, t);
    __syncthreads();

    for (int i = t; i < 8256; i += 256) {
        int r = (int)((sqrtf(8.0f * (float)i + 1.0f) - 1.0f) * 0.5f);
        if ((r + 1) * (r + 2) / 2 <= i) r++;
        if (r * (r + 1) / 2 > i) r--;
        int c = i - r * (r + 1) / 2;
        float a = F32[r * F32S + c], b = F32[c * F32S + r];
        float g = 0.5f * (a + b);
        F32[r * F32S + c] = g;
        F32[c * F32S + r] = g;
    }
    if (t < CI)
        sv_q[t] = dot_packed(P1h, P1l, t, sv_s) + 4096.0f * sv_tb[t];
    __syncthreads();

    pack_from_smem(F32, P0h, P0l, t);
    __syncthreads();

    mgh3(P1h, P1l, P0h, P0l, F32, t);
    __syncthreads();

    pack_from_smem(F32, P0h, P0l, t);
    stage_pack_gmem(phi_w, P1h, P1l, t);
    __syncthreads();
    if (t < CI)
        sv_u[t] = dot_packed(P1h, P1l, t, sv_s);
    __syncthreads();

    mgh3(P1h, P1l, P0h, P0l, F32, t);
    __syncthreads();

    if (t < CI) {
        const float w1 = sv_u[t];
        const float w2 = phi_b[t];
        float* rowp = F32 + t * F32S;
        float mx = -1e30f;
#pragma unroll 8
        for (int d = 0; d < 128; d++) {
            float v = rowp[d] + w1 * sv_tb[d] + w2 * sv_q[d];
            rowp[d] = v;
            mx = fmaxf(mx, v);
        }
        float ssum = 0.f;
#pragma unroll 8
        for (int d = 0; d < 128; d++) {
            float ev = expf(rowp[d] - mx);
            rowp[d] = ev;
            ssum += ev;
        }
        const float inv = 1.0f / ssum;
        float cacc = 0.f;
#pragma unroll
        for (int p = 0; p < 64; p++) {
            float f0 = rowp[2 * p] * inv;
            float f1 = rowp[2 * p + 1] * inv;
            cacc += f0 * sv_gb[2 * p] + f1 * sv_gb[2 * p + 1];
            unsigned h, l;
            split2(f0, f1, h, l);
            P1h[t * APR + p] = h;
            P1l[t * APR + p] = l;
        }
        sv_c[t] = cacc;
    }
    __syncthreads();

    for (int idx = t; idx < CI * CI; idx += 256)
        F32[(idx >> 7) * F32S + (idx & 127)] = g_w[idx];
    __syncthreads();
    {
        const int k = t >> 1, d0 = (t & 1) * 64;
        const int base = k * APR + d0 / 2;
#pragma unroll
        for (int p = 0; p < 32; p++) {
            const int d = d0 + 2 * p;
            unsigned h, l;
            split2(F32[d * F32S + k], F32[(d + 1) * F32S + k], h, l);
            P0h[base + p] = h;
            P0l[base + p] = l;
        }
    }
    __syncthreads();

    mgh3(P0h, P0l, P1h, P1l, F32, t);
    __syncthreads();

    pack_from_smem(F32, P0h, P0l, t);
    stage_pack_gmem(W_w, P1h, P1l, t);
    __syncthreads();
    if (t < CI) {
        float b0 = dot_packed(P1h, P1l, t, sv_c);
        float sc = sv_scale[t];
        g_bvec[bb * CI + t] = sc * (b0 + W_b[t]) + bn_beta[t] - bn_mean[t] * sc;
    }

    mgh3_final(P1h, P1l, P0h, P0l,
               g_Ah2 + (size_t)bb * CI * 64, g_Al2 + (size_t)bb * CI * 64,
               sv_scale, t);
}

// =====================================================================
// Kernel 3: Z = A'' X + b' via fp16 3-product + ldmatrix, single wave.
// grid (2, 64), 512 threads. A'' resident. X chunks stored [ch][px]
// (32 rows x 128 uints, stride XST2); B frags via ldmatrix.x4.trans.
// =====================================================================
#define AP_SMEM ((2 * 128 * APR + 4 * 32 * XST2) * 4)   // 137216 B

__global__ void __launch_bounds__(512)
apply_kernel(const float* __restrict__ X, float* __restrict__ Z)
{
    extern __shared__ unsigned apsm[];
    unsigned* sAh = apsm;                       // [128][APR]
    unsigned* sAl = sAh + 128 * APR;
    unsigned* sXh[2] = {sAl + 128 * APR, sAl + 128 * APR + 32 * XST2};
    unsigned* sXl[2] = {sAl + 128 * APR + 2 * 32 * XST2,
                        sAl + 128 * APR + 3 * 32 * XST2};

    const int t = threadIdx.x;
    const int lane = t & 31, w = t >> 5;
    const int wr = (w >> 2) * 32;
    const int wc = (w & 3) * 64;
    const int qr = lane >> 2, qc = lane & 3;
    const int bb = blockIdx.y;
    const int half0 = blockIdx.x * 2048;

    const uint32_t aAh = s2u(sAh), aAl = s2u(sAl);
    const uint32_t aXh[2] = {s2u(sXh[0]), s2u(sXh[1])};
    const uint32_t aXl[2] = {s2u(sXl[0]), s2u(sXl[1])};

    // per-lane ldmatrix offsets
    uint32_t aoffA[2][2];   // [m][ks] (g term added in loop: g*64 bytes)
#pragma unroll
    for (int m = 0; m < 2; m++)
#pragma unroll
        for (int ks = 0; ks < 2; ks++)
            aoffA[m][ks] = (uint32_t)((wr + m * 16 + (lane & 15)) * APR + ks * 8) * 4u
                         + (uint32_t)((lane >> 4) & 1) * 16u;
    uint32_t boffB[2][4];   // [ks][j]
#pragma unroll
    for (int ks = 0; ks < 2; ks++)
#pragma unroll
        for (int j = 0; j < 4; j++)
            boffB[ks][j] = (uint32_t)((ks * 16 + (lane & 7) + ((lane >> 3) & 1) * 8) * XST2) * 4u
                         + (uint32_t)(wc + j * 16 + ((lane >> 4) & 1) * 8) * 2u;

    // ---- stage A'' hi/lo resident ONCE ----
    {
        const int row = t >> 2, seg = (t & 3) * 16;
        const uint4* Ah = (const uint4*)(g_Ah2 + ((size_t)bb * CI + row) * 64 + seg);
        const uint4* Al = (const uint4*)(g_Al2 + ((size_t)bb * CI + row) * 64 + seg);
#pragma unroll
        for (int j = 0; j < 4; j++) {
            *(uint4*)&sAh[row * APR + seg + 4 * j] = Ah[j];
            *(uint4*)&sAl[row * APR + seg + 4 * j] = Al[j];
        }
    }

    float bias[2][2];
#pragma unroll
    for (int m = 0; m < 2; m++) {
        bias[m][0] = g_bvec[bb * CI + wr + m * 16 + qr];
        bias[m][1] = g_bvec[bb * CI + wr + m * 16 + qr + 8];
    }

    const float* Xb = X + (size_t)bb * CI * NPIX;
    float* Zb = Z + (size_t)bb * CI * NPIX;

    const int lp = w;              // ch-pair row 0..15 (ch 2lp, 2lp+1)
    const int lpx = lane * 8;      // 8 px per lane

    float acc[2][8][4];
#pragma unroll
    for (int m = 0; m < 2; m++)
#pragma unroll
        for (int n = 0; n < 8; n++)
#pragma unroll
            for (int r = 0; r < 4; r++) acc[m][n][r] = 0.f;

    // converter: rows 2lp / 2lp+1, px lpx..+7 -> 4 uints each (px-pair halves)
    {
        const float* se = Xb + (size_t)(2 * lp) * NPIX + half0 + lpx;
        const float* so = se + NPIX;
        float4 e0 = *(const float4*)(se), e1 = *(const float4*)(se + 4);
        float4 o0 = *(const float4*)(so), o1 = *(const float4*)(so + 4);
        unsigned hE[4], lE[4], hO[4], lO[4];
        split2(e0.x, e0.y, hE[0], lE[0]); split2(e0.z, e0.w, hE[1], lE[1]);
        split2(e1.x, e1.y, hE[2], lE[2]); split2(e1.z, e1.w, hE[3], lE[3]);
        split2(o0.x, o0.y, hO[0], lO[0]); split2(o0.z, o0.w, hO[1], lO[1]);
        split2(o1.x, o1.y, hO[2], lO[2]); split2(o1.z, o1.w, hO[3], lO[3]);
        *(uint4*)&sXh[0][(2 * lp) * XST2 + lane * 4]     = make_uint4(hE[0], hE[1], hE[2], hE[3]);
        *(uint4*)&sXh[0][(2 * lp + 1) * XST2 + lane * 4] = make_uint4(hO[0], hO[1], hO[2], hO[3]);
        *(uint4*)&sXl[0][(2 * lp) * XST2 + lane * 4]     = make_uint4(lE[0], lE[1], lE[2], lE[3]);
        *(uint4*)&sXl[0][(2 * lp + 1) * XST2 + lane * 4] = make_uint4(lO[0], lO[1], lO[2], lO[3]);
    }
    __syncthreads();

    for (int c = 0; c < 32; c++) {
        const int b = c & 1;
        const int g = c & 3;

        float4 ne0, ne1, no0, no1;
        if (c < 31) {
            const int ng = (c + 1) & 3, ns = (c + 1) >> 2;
            const float* se = Xb + (size_t)(ng * 32 + 2 * lp) * NPIX + half0 + ns * 256 + lpx;
            const float* so = se + NPIX;
            ne0 = *(const float4*)(se); ne1 = *(const float4*)(se + 4);
            no0 = *(const float4*)(so); no1 = *(const float4*)(so + 4);
        }

        const uint32_t gOff = (uint32_t)g * 64u;   // g*16 uint pairs = 64 bytes
#pragma unroll
        for (int ks = 0; ks < 2; ks++) {
            unsigned Ahf[2][4], Alf[2][4];
#pragma unroll
            for (int m = 0; m < 2; m++) {
                LDSM_X4(Ahf[m], aAh + aoffA[m][ks] + gOff);
                LDSM_X4(Alf[m], aAl + aoffA[m][ks] + gOff);
            }
#pragma unroll
            for (int j = 0; j < 4; j++) {
                unsigned BH[4], BL[4];
                LDSM_X4T(BH, aXh[b] + boffB[ks][j]);
                LDSM_X4T(BL, aXl[b] + boffB[ks][j]);
                unsigned B0h[2] = {BH[0], BH[1]}, B1h[2] = {BH[2], BH[3]};
                unsigned B0l[2] = {BL[0], BL[1]}, B1l[2] = {BL[2], BL[3]};
#pragma unroll
                for (int m = 0; m < 2; m++) {
                    mmah(acc[m][2 * j],     Ahf[m], B0h);
                    mmah(acc[m][2 * j],     Ahf[m], B0l);
                    mmah(acc[m][2 * j],     Alf[m], B0h);
                    mmah(acc[m][2 * j + 1], Ahf[m], B1h);
                    mmah(acc[m][2 * j + 1], Ahf[m], B1l);
                    mmah(acc[m][2 * j + 1], Alf[m], B1h);
                }
            }
        }

        if (c < 31) {
            unsigned hE[4], lE[4], hO[4], lO[4];
            split2(ne0.x, ne0.y, hE[0], lE[0]); split2(ne0.z, ne0.w, hE[1], lE[1]);
            split2(ne1.x, ne1.y, hE[2], lE[2]); split2(ne1.z, ne1.w, hE[3], lE[3]);
            split2(no0.x, no0.y, hO[0], lO[0]); split2(no0.z, no0.w, hO[1], lO[1]);
            split2(no1.x, no1.y, hO[2], lO[2]); split2(no1.z, no1.w, hO[3], lO[3]);
            *(uint4*)&sXh[b ^ 1][(2 * lp) * XST2 + lane * 4]     = make_uint4(hE[0], hE[1], hE[2], hE[3]);
            *(uint4*)&sXh[b ^ 1][(2 * lp + 1) * XST2 + lane * 4] = make_uint4(hO[0], hO[1], hO[2], hO[3]);
            *(uint4*)&sXl[b ^ 1][(2 * lp) * XST2 + lane * 4]     = make_uint4(lE[0], lE[1], lE[2], lE[3]);
            *(uint4*)&sXl[b ^ 1][(2 * lp + 1) * XST2 + lane * 4] = make_uint4(lO[0], lO[1], lO[2], lO[3]);
        }
        __syncthreads();

        if (g == 3) {
            const int px0 = half0 + (c >> 2) * 256;
#pragma unroll
            for (int m = 0; m < 2; m++) {
                const int r0 = wr + m * 16 + qr;
#pragma unroll
                for (int n = 0; n < 8; n++) {
                    const int c0 = px0 + wc + n * 8 + qc * 2;
                    *(float2*)(Zb + (size_t)r0 * NPIX + c0) =
                        make_float2(acc[m][n][0] + bias[m][0], acc[m][n][1] + bias[m][0]);
                    *(float2*)(Zb + (size_t)(r0 + 8) * NPIX + c0) =
                        make_float2(acc[m][n][2] + bias[m][1], acc[m][n][3] + bias[m][1]);
                }
            }
#pragma unroll
            for (int m = 0; m < 2; m++)
#pragma unroll
                for (int n = 0; n < 8; n++)
#pragma unroll
                    for (int r = 0; r < 4; r++) acc[m][n][r] = 0.f;
        }
    }
}

// =====================================================================
extern "C" void kernel_launch(void* const* d_in, const int* in_sizes, int n_in,
                              void* d_out, int out_size)
{
    (void)in_sizes; (void)n_in; (void)out_size;
    const float* x        = (const float*)d_in[0];
    const float* theta_w  = (const float*)d_in[1];
    const float* theta_b  = (const float*)d_in[2];
    const float* phi_w    = (const float*)d_in[3];
    const float* phi_b    = (const float*)d_in[4];
    const float* g_w      = (const float*)d_in[5];
    const float* g_b      = (const float*)d_in[6];
    const float* W_w      = (const float*)d_in[7];
    const float* W_b      = (const float*)d_in[8];
    const float* bn_gamma = (const float*)d_in[9];
    const float* bn_beta  = (const float*)d_in[10];
    const float* bn_mean  = (const float*)d_in[11];
    const float* bn_var   = (const float*)d_in[12];
    float* out = (float*)d_out;

    cudaFuncSetAttribute(chain_kernel,
                         cudaFuncAttributeMaxDynamicSharedMemorySize, CH_SMEM);
    cudaFuncSetAttribute(apply_kernel,
                         cudaFuncAttributeMaxDynamicSharedMemorySize, AP_SMEM);

    gram_kernel<<<dim3(KSPLIT, NB), 256>>>(x);
    chain_kernel<<<NB, 256, CH_SMEM>>>(theta_w, theta_b, phi_w, phi_b,
                                       g_w, g_b, W_w, W_b,
                                       bn_gamma, bn_beta, bn_mean, bn_var);
    apply_kernel<<<dim3(2, NB), 512, AP_SMEM>>>(x, out);
}